// round 3
// baseline (speedup 1.0000x reference)
#include <cuda_runtime.h>
#include <cstdint>

// Problem constants
constexpr int B = 128, L = 1024, V = 512, H = 512, C = 20;
constexpr int H3 = 3 * H;          // 1536
constexpr int NROW = L * B;        // 131072

// ---------------------------------------------------------------------------
// Device scratch
// ---------------------------------------------------------------------------
__device__ float g_T[3][V][H];                    // transposed conv weights
__device__ float g_y[(size_t)NROW * H];           // conv output
__device__ float g_gi[(size_t)NROW * H3];         // input-side gate preacts
__device__ float g_h[2][B * H];                   // double-buffered hidden state
__device__ unsigned g_bar_count;
__device__ unsigned g_bar_gen;

// ---------------------------------------------------------------------------
// Helpers
// ---------------------------------------------------------------------------
__device__ __forceinline__ float to_tf32(float x) {
    uint32_t u;
    asm("cvt.rna.tf32.f32 %0, %1;" : "=r"(u) : "f"(x));
    return __uint_as_float(u);
}

__device__ __forceinline__ void mma_tf32(float c[4], const uint32_t a[4], const uint32_t b[2]) {
    asm volatile(
        "mma.sync.aligned.m16n8k8.row.col.f32.tf32.tf32.f32 "
        "{%0,%1,%2,%3}, {%4,%5,%6,%7}, {%8,%9}, {%0,%1,%2,%3};\n"
        : "+f"(c[0]), "+f"(c[1]), "+f"(c[2]), "+f"(c[3])
        : "r"(a[0]), "r"(a[1]), "r"(a[2]), "r"(a[3]), "r"(b[0]), "r"(b[1]));
}

__device__ __forceinline__ void cp16(float* dst_smem, const float* src) {
    uint32_t d = (uint32_t)__cvta_generic_to_shared(dst_smem);
    asm volatile("cp.async.cg.shared.global [%0], [%1], 16;" :: "r"(d), "l"(src));
}

// ---------------------------------------------------------------------------
// Init (runs every launch — graph replays)
// ---------------------------------------------------------------------------
__global__ void init_kernel() {
    const int i = blockIdx.x * blockDim.x + threadIdx.x;
    if (i < 2 * B * H) ((float*)g_h)[i] = 0.0f;
    if (i == 0) { g_bar_count = 0u; g_bar_gen = 0u; }
}

// ---------------------------------------------------------------------------
// Transpose conv_w (H,V,3) -> g_T[k][v][h]
// ---------------------------------------------------------------------------
__global__ void transpose_kernel(const float* __restrict__ conv_w) {
    const int idx = blockIdx.x * blockDim.x + threadIdx.x;
    if (idx < H * V * 3) {
        const int k = idx % 3;
        const int v = (idx / 3) % V;
        const int h = idx / (3 * V);
        g_T[k][v][h] = conv_w[idx];
    }
}

// ---------------------------------------------------------------------------
// Embedding "conv"
// ---------------------------------------------------------------------------
__global__ void embed_kernel(const int* __restrict__ x, const float* __restrict__ conv_b) {
    const int n = blockIdx.x;      // n = t*B + b
    const int t = n >> 7;
    const int b = n & 127;
    const int x0 = x[b * L + t];
    const int xm = (t > 0) ? x[b * L + t - 1] : -1;
    const int xp = (t < L - 1) ? x[b * L + t + 1] : -1;
    const int hb = threadIdx.x * 4;

    float4 acc = *(const float4*)(conv_b + hb);
    {
        const float4 e = *(const float4*)(&g_T[1][x0][hb]);
        acc.x += e.x; acc.y += e.y; acc.z += e.z; acc.w += e.w;
    }
    if (xm >= 0) {
        const float4 e = *(const float4*)(&g_T[0][xm][hb]);
        acc.x += e.x; acc.y += e.y; acc.z += e.z; acc.w += e.w;
    }
    if (xp >= 0) {
        const float4 e = *(const float4*)(&g_T[2][xp][hb]);
        acc.x += e.x; acc.y += e.y; acc.z += e.z; acc.w += e.w;
    }
    acc.x = fmaxf(acc.x, 0.0f);
    acc.y = fmaxf(acc.y, 0.0f);
    acc.z = fmaxf(acc.z, 0.0f);
    acc.w = fmaxf(acc.w, 0.0f);
    *(float4*)(g_y + (size_t)n * H + hb) = acc;
}

// ---------------------------------------------------------------------------
// gi = y @ w_ih^T + b_ih  (unchanged from R1 — known working)
// ---------------------------------------------------------------------------
__global__ void __launch_bounds__(256) gi_gemm_kernel(const float* __restrict__ w_ih,
                                                      const float* __restrict__ b_ih) {
    __shared__ float As[128][36];
    __shared__ float Bs[64][36];
    const int tid = threadIdx.x;
    const int warp = tid >> 5, lane = tid & 31;
    const int g = lane >> 2, tig = lane & 3;
    const int wm = (warp >> 1) * 32;
    const int wn = (warp & 1) * 32;
    const size_t row0 = (size_t)blockIdx.y * 128;
    const int col0 = blockIdx.x * 64;

    float c[2][4][4];
#pragma unroll
    for (int mi = 0; mi < 2; mi++)
#pragma unroll
        for (int ni = 0; ni < 4; ni++)
#pragma unroll
            for (int q = 0; q < 4; q++) c[mi][ni][q] = 0.0f;

    const int ar = tid >> 3;
    const int ac = (tid & 7) * 4;
    const float* Ap = g_y + (row0 + ar) * H + ac;
    const float* Bp = w_ih + (size_t)(col0 + ar) * H + ac;

    float4 apf[4], bpf[2];
#pragma unroll
    for (int i = 0; i < 4; i++) apf[i] = *(const float4*)(Ap + (size_t)(32 * i) * H);
#pragma unroll
    for (int i = 0; i < 2; i++) bpf[i] = *(const float4*)(Bp + (size_t)(32 * i) * H);

    for (int kt = 0; kt < 16; kt++) {
#pragma unroll
        for (int i = 0; i < 4; i++) {
            float* d = &As[ar + 32 * i][ac];
            d[0] = to_tf32(apf[i].x); d[1] = to_tf32(apf[i].y);
            d[2] = to_tf32(apf[i].z); d[3] = to_tf32(apf[i].w);
        }
#pragma unroll
        for (int i = 0; i < 2; i++) {
            float* d = &Bs[ar + 32 * i][ac];
            d[0] = to_tf32(bpf[i].x); d[1] = to_tf32(bpf[i].y);
            d[2] = to_tf32(bpf[i].z); d[3] = to_tf32(bpf[i].w);
        }
        __syncthreads();
        if (kt < 15) {
            const float* Ap2 = Ap + (kt + 1) * 32;
            const float* Bp2 = Bp + (kt + 1) * 32;
#pragma unroll
            for (int i = 0; i < 4; i++) apf[i] = *(const float4*)(Ap2 + (size_t)(32 * i) * H);
#pragma unroll
            for (int i = 0; i < 2; i++) bpf[i] = *(const float4*)(Bp2 + (size_t)(32 * i) * H);
        }
#pragma unroll
        for (int k8 = 0; k8 < 4; k8++) {
            const int kk = k8 * 8 + tig;
            uint32_t a[2][4];
#pragma unroll
            for (int mi = 0; mi < 2; mi++) {
                const int r0 = wm + mi * 16;
                a[mi][0] = __float_as_uint(As[r0 + g][kk]);
                a[mi][1] = __float_as_uint(As[r0 + g + 8][kk]);
                a[mi][2] = __float_as_uint(As[r0 + g][kk + 4]);
                a[mi][3] = __float_as_uint(As[r0 + g + 8][kk + 4]);
            }
#pragma unroll
            for (int ni = 0; ni < 4; ni++) {
                uint32_t bb[2];
                const int nr = wn + ni * 8 + g;
                bb[0] = __float_as_uint(Bs[nr][kk]);
                bb[1] = __float_as_uint(Bs[nr][kk + 4]);
#pragma unroll
                for (int mi = 0; mi < 2; mi++) mma_tf32(c[mi][ni], a[mi], bb);
            }
        }
        __syncthreads();
    }
#pragma unroll
    for (int mi = 0; mi < 2; mi++) {
        const size_t r0 = row0 + wm + mi * 16 + g;
#pragma unroll
        for (int ni = 0; ni < 4; ni++) {
            const int cc = col0 + wn + ni * 8 + 2 * tig;
            const float b0 = b_ih[cc], b1 = b_ih[cc + 1];
            float* C0 = g_gi + r0 * H3 + cc;
            float* C1 = g_gi + (r0 + 8) * H3 + cc;
            C0[0] = c[mi][ni][0] + b0; C0[1] = c[mi][ni][1] + b1;
            C1[0] = c[mi][ni][2] + b0; C1[1] = c[mi][ni][3] + b1;
        }
    }
}

// ---------------------------------------------------------------------------
// Persistent GRU kernel v2: 64 CTAs x 128 threads (4 warps, m32 x n24 each).
// w_hh slice resident in SMEM; h broadcast via cp.async 4-stage ring (L2-
// coherent); spin barrier (no nanosleep); gi/h_old prefetched per step.
// ---------------------------------------------------------------------------
constexpr int GCTAS = 64;
constexpr int WC_LD = 516;       // weights stride (floats)
constexpr int HS_LD = 36;        // h-tile stride (floats)
constexpr int NSTG = 4;          // cp.async ring depth
constexpr int GRU_SMEM = (24 * WC_LD + NSTG * 128 * HS_LD) * 4;   // 123264 B

__device__ __forceinline__ void issue_cp(const float* hcur, int kc, int buf,
                                         float* Hs, int r8, int t8) {
    float* dst = Hs + buf * (128 * HS_LD) + t8 * 4;
    const float* src = hcur + kc * 32 + t8 * 4;
#pragma unroll
    for (int pp = 0; pp < 8; pp++) {
        const int r = r8 + 16 * pp;
        cp16(dst + r * HS_LD, src + r * H);
    }
    asm volatile("cp.async.commit_group;" ::: "memory");
}

__global__ void __launch_bounds__(128, 1) gru_kernel(const float* __restrict__ w_hh,
                                                     const float* __restrict__ b_hh) {
    extern __shared__ float sm[];
    float* Wc = sm;                       // [24][WC_LD] weights (r,z,n strips)
    float* Hs = sm + 24 * WC_LD;          // [NSTG][128][HS_LD]

    const int tid = threadIdx.x;
    const int warp = tid >> 5, lane = tid & 31;
    const int g = lane >> 2, tig = lane & 3;
    const int rb = warp * 32;
    const int j0 = blockIdx.x * 8;
    const int r8 = tid >> 3, t8 = tid & 7;

    // Load w_hh slice (raw fp32; HMMA truncates to tf32 itself)
    for (int i = tid; i < 24 * H; i += 128) {
        const int lr = i >> 9, k = i & 511;
        Wc[lr * WC_LD + k] = w_hh[(size_t)((lr >> 3) * H + j0 + (lr & 7)) * H + k];
    }
    const int Jb = j0 + 2 * tig;
    float2 bh[3];
    bh[0] = *(const float2*)(b_hh + Jb);
    bh[1] = *(const float2*)(b_hh + H + Jb);
    bh[2] = *(const float2*)(b_hh + 2 * H + Jb);
    __syncthreads();

    int p = 0;
    for (int t = 0; t < L; t++) {
        const float* hcur = g_h[p];
        float* hnxt = g_h[p ^ 1];

        // Prefetch this step's gi and h_old (own columns — written by this SM)
        const float* gi_t = g_gi + (size_t)t * (B * H3);
        float2 gv[4][3], hold[4];
#pragma unroll
        for (int ro = 0; ro < 4; ro++) {
            const int R = rb + (ro >> 1) * 16 + (ro & 1) * 8 + g;
            const float* gr = gi_t + (size_t)R * H3;
            gv[ro][0] = *(const float2*)(gr + Jb);
            gv[ro][1] = *(const float2*)(gr + H + Jb);
            gv[ro][2] = *(const float2*)(gr + 2 * H + Jb);
            hold[ro] = *(const float2*)(hcur + R * H + Jb);
        }

        // cp.async ring prologue: stages 0..2
#pragma unroll
        for (int s = 0; s < 3; s++) issue_cp(hcur, s, s, Hs, r8, t8);

        float c[2][3][4] = {};
#pragma unroll 4
        for (int kc = 0; kc < 16; kc++) {
            asm volatile("cp.async.wait_group 2;" ::: "memory");
            __syncthreads();
            const float* Hb = Hs + (kc & 3) * (128 * HS_LD);
#pragma unroll
            for (int k8 = 0; k8 < 4; k8++) {
                const int kk = k8 * 8 + tig;
                uint32_t a[2][4];
#pragma unroll
                for (int mi = 0; mi < 2; mi++) {
                    const float* hb = Hb + (rb + mi * 16 + g) * HS_LD;
                    a[mi][0] = __float_as_uint(hb[kk]);
                    a[mi][1] = __float_as_uint(hb[8 * HS_LD + kk]);
                    a[mi][2] = __float_as_uint(hb[kk + 4]);
                    a[mi][3] = __float_as_uint(hb[8 * HS_LD + kk + 4]);
                }
#pragma unroll
                for (int nb = 0; nb < 3; nb++) {
                    const float* wr = Wc + (nb * 8 + g) * WC_LD + kc * 32;
                    uint32_t bb[2];
                    bb[0] = __float_as_uint(wr[kk]);
                    bb[1] = __float_as_uint(wr[kk + 4]);
                    mma_tf32(c[0][nb], a[0], bb);
                    mma_tf32(c[1][nb], a[1], bb);
                }
            }
            if (kc < 13) issue_cp(hcur, kc + 3, (kc + 3) & 3, Hs, r8, t8);
            else asm volatile("cp.async.commit_group;" ::: "memory");
        }

        // Gates + state update. Thread owns rows {rb+g, +8, +16, +24}, cols {Jb, Jb+1}.
#pragma unroll
        for (int ro = 0; ro < 4; ro++) {
            const int R = rb + (ro >> 1) * 16 + (ro & 1) * 8 + g;
            const int mi = ro >> 1, fo = (ro & 1) * 2;
            const float ghr0 = c[mi][0][fo] + bh[0].x, ghr1 = c[mi][0][fo + 1] + bh[0].y;
            const float ghz0 = c[mi][1][fo] + bh[1].x, ghz1 = c[mi][1][fo + 1] + bh[1].y;
            const float ghn0 = c[mi][2][fo] + bh[2].x, ghn1 = c[mi][2][fo + 1] + bh[2].y;
            const float r0 = 1.0f / (1.0f + __expf(-(gv[ro][0].x + ghr0)));
            const float r1 = 1.0f / (1.0f + __expf(-(gv[ro][0].y + ghr1)));
            const float z0 = 1.0f / (1.0f + __expf(-(gv[ro][1].x + ghz0)));
            const float z1 = 1.0f / (1.0f + __expf(-(gv[ro][1].y + ghz1)));
            const float n0 = tanhf(gv[ro][2].x + r0 * ghn0);
            const float n1 = tanhf(gv[ro][2].y + r1 * ghn1);
            float2 hn;
            hn.x = (1.0f - z0) * n0 + z0 * hold[ro].x;
            hn.y = (1.0f - z1) * n1 + z1 * hold[ro].y;
            *(float2*)(hnxt + R * H + Jb) = hn;
        }

        // Grid barrier: tight spin, no nanosleep
        __threadfence();
        __syncthreads();
        if (tid == 0) {
            const unsigned target = (unsigned)(t + 1);
            if (atomicAdd(&g_bar_count, 1u) == GCTAS - 1) {
                atomicExch(&g_bar_count, 0u);
                __threadfence();
                atomicExch(&g_bar_gen, target);
            } else {
                while (*(volatile unsigned*)&g_bar_gen < target) {}
            }
        }
        __syncthreads();
        p ^= 1;
    }
}

// ---------------------------------------------------------------------------
// Classifier
// ---------------------------------------------------------------------------
__global__ void classifier_kernel(const float* __restrict__ cls_w,
                                  const float* __restrict__ cls_b,
                                  float* __restrict__ out) {
    const int b = blockIdx.x / C;
    const int cc = blockIdx.x % C;
    const float* h = g_h[0] + b * H;
    const float* w = cls_w + cc * H;
    float s = 0.0f;
    for (int k = threadIdx.x; k < H; k += 64) s += h[k] * w[k];
#pragma unroll
    for (int o = 16; o > 0; o >>= 1) s += __shfl_down_sync(0xffffffffu, s, o);
    __shared__ float red[2];
    if ((threadIdx.x & 31) == 0) red[threadIdx.x >> 5] = s;
    __syncthreads();
    if (threadIdx.x == 0) out[b * C + cc] = red[0] + red[1] + cls_b[cc];
}

// ---------------------------------------------------------------------------
// Launch
// ---------------------------------------------------------------------------
extern "C" void kernel_launch(void* const* d_in, const int* in_sizes, int n_in,
                              void* d_out, int out_size) {
    const int*   x      = (const int*)d_in[0];
    const float* conv_w = (const float*)d_in[1];
    const float* conv_b = (const float*)d_in[2];
    const float* w_ih   = (const float*)d_in[3];
    const float* w_hh   = (const float*)d_in[4];
    const float* b_ih   = (const float*)d_in[5];
    const float* b_hh   = (const float*)d_in[6];
    const float* cls_w  = (const float*)d_in[7];
    const float* cls_b  = (const float*)d_in[8];
    float* out = (float*)d_out;

    cudaFuncSetAttribute(gru_kernel, cudaFuncAttributeMaxDynamicSharedMemorySize, GRU_SMEM);

    init_kernel<<<512, 256>>>();
    transpose_kernel<<<(H * V * 3 + 255) / 256, 256>>>(conv_w);
    embed_kernel<<<NROW, 128>>>(x, conv_b);
    gi_gemm_kernel<<<dim3(H3 / 64, NROW / 128), 256>>>(w_ih, b_ih);
    gru_kernel<<<GCTAS, 128, GRU_SMEM>>>(w_hh, b_hh);
    classifier_kernel<<<B * C, 64>>>(cls_w, cls_b, out);
}

// round 4
// speedup vs baseline: 1.0293x; 1.0293x over previous
#include <cuda_runtime.h>
#include <cstdint>

// Problem constants
constexpr int B = 128, L = 1024, V = 512, H = 512, C = 20;
constexpr int H3 = 3 * H;          // 1536
constexpr int NROW = L * B;        // 131072

// ---------------------------------------------------------------------------
// Device scratch
// ---------------------------------------------------------------------------
__device__ float g_T[3][V][H];                    // transposed conv weights
__device__ float g_y[(size_t)NROW * H];           // conv output
__device__ float g_gi[(size_t)NROW * H3];         // input-side gate preacts
__device__ float g_h[2][B * H];                   // double-buffered hidden state
__device__ unsigned g_bar_count;
__device__ unsigned g_bar_gen;

// ---------------------------------------------------------------------------
// Helpers
// ---------------------------------------------------------------------------
__device__ __forceinline__ float to_tf32(float x) {
    uint32_t u;
    asm("cvt.rna.tf32.f32 %0, %1;" : "=r"(u) : "f"(x));
    return __uint_as_float(u);
}

__device__ __forceinline__ void mma_tf32(float c[4], const uint32_t a[4], const uint32_t b[2]) {
    asm volatile(
        "mma.sync.aligned.m16n8k8.row.col.f32.tf32.tf32.f32 "
        "{%0,%1,%2,%3}, {%4,%5,%6,%7}, {%8,%9}, {%0,%1,%2,%3};\n"
        : "+f"(c[0]), "+f"(c[1]), "+f"(c[2]), "+f"(c[3])
        : "r"(a[0]), "r"(a[1]), "r"(a[2]), "r"(a[3]), "r"(b[0]), "r"(b[1]));
}

__device__ __forceinline__ void cp16(float* dst_smem, const float* src) {
    uint32_t d = (uint32_t)__cvta_generic_to_shared(dst_smem);
    asm volatile("cp.async.cg.shared.global [%0], [%1], 16;" :: "r"(d), "l"(src));
}

// ---------------------------------------------------------------------------
// Init (runs every launch — graph replays)
// ---------------------------------------------------------------------------
__global__ void init_kernel() {
    const int i = blockIdx.x * blockDim.x + threadIdx.x;
    if (i < 2 * B * H) ((float*)g_h)[i] = 0.0f;
    if (i == 0) { g_bar_count = 0u; g_bar_gen = 0u; }
}

// ---------------------------------------------------------------------------
// Transpose conv_w (H,V,3) -> g_T[k][v][h]
// ---------------------------------------------------------------------------
__global__ void transpose_kernel(const float* __restrict__ conv_w) {
    const int idx = blockIdx.x * blockDim.x + threadIdx.x;
    if (idx < H * V * 3) {
        const int k = idx % 3;
        const int v = (idx / 3) % V;
        const int h = idx / (3 * V);
        g_T[k][v][h] = conv_w[idx];
    }
}

// ---------------------------------------------------------------------------
// Embedding "conv"
// ---------------------------------------------------------------------------
__global__ void embed_kernel(const int* __restrict__ x, const float* __restrict__ conv_b) {
    const int n = blockIdx.x;      // n = t*B + b
    const int t = n >> 7;
    const int b = n & 127;
    const int x0 = x[b * L + t];
    const int xm = (t > 0) ? x[b * L + t - 1] : -1;
    const int xp = (t < L - 1) ? x[b * L + t + 1] : -1;
    const int hb = threadIdx.x * 4;

    float4 acc = *(const float4*)(conv_b + hb);
    {
        const float4 e = *(const float4*)(&g_T[1][x0][hb]);
        acc.x += e.x; acc.y += e.y; acc.z += e.z; acc.w += e.w;
    }
    if (xm >= 0) {
        const float4 e = *(const float4*)(&g_T[0][xm][hb]);
        acc.x += e.x; acc.y += e.y; acc.z += e.z; acc.w += e.w;
    }
    if (xp >= 0) {
        const float4 e = *(const float4*)(&g_T[2][xp][hb]);
        acc.x += e.x; acc.y += e.y; acc.z += e.z; acc.w += e.w;
    }
    acc.x = fmaxf(acc.x, 0.0f);
    acc.y = fmaxf(acc.y, 0.0f);
    acc.z = fmaxf(acc.z, 0.0f);
    acc.w = fmaxf(acc.w, 0.0f);
    *(float4*)(g_y + (size_t)n * H + hb) = acc;
}

// ---------------------------------------------------------------------------
// gi = y @ w_ih^T + b_ih  (unchanged — known working)
// ---------------------------------------------------------------------------
__global__ void __launch_bounds__(256) gi_gemm_kernel(const float* __restrict__ w_ih,
                                                      const float* __restrict__ b_ih) {
    __shared__ float As[128][36];
    __shared__ float Bs[64][36];
    const int tid = threadIdx.x;
    const int warp = tid >> 5, lane = tid & 31;
    const int g = lane >> 2, tig = lane & 3;
    const int wm = (warp >> 1) * 32;
    const int wn = (warp & 1) * 32;
    const size_t row0 = (size_t)blockIdx.y * 128;
    const int col0 = blockIdx.x * 64;

    float c[2][4][4];
#pragma unroll
    for (int mi = 0; mi < 2; mi++)
#pragma unroll
        for (int ni = 0; ni < 4; ni++)
#pragma unroll
            for (int q = 0; q < 4; q++) c[mi][ni][q] = 0.0f;

    const int ar = tid >> 3;
    const int ac = (tid & 7) * 4;
    const float* Ap = g_y + (row0 + ar) * H + ac;
    const float* Bp = w_ih + (size_t)(col0 + ar) * H + ac;

    float4 apf[4], bpf[2];
#pragma unroll
    for (int i = 0; i < 4; i++) apf[i] = *(const float4*)(Ap + (size_t)(32 * i) * H);
#pragma unroll
    for (int i = 0; i < 2; i++) bpf[i] = *(const float4*)(Bp + (size_t)(32 * i) * H);

    for (int kt = 0; kt < 16; kt++) {
#pragma unroll
        for (int i = 0; i < 4; i++) {
            float* d = &As[ar + 32 * i][ac];
            d[0] = to_tf32(apf[i].x); d[1] = to_tf32(apf[i].y);
            d[2] = to_tf32(apf[i].z); d[3] = to_tf32(apf[i].w);
        }
#pragma unroll
        for (int i = 0; i < 2; i++) {
            float* d = &Bs[ar + 32 * i][ac];
            d[0] = to_tf32(bpf[i].x); d[1] = to_tf32(bpf[i].y);
            d[2] = to_tf32(bpf[i].z); d[3] = to_tf32(bpf[i].w);
        }
        __syncthreads();
        if (kt < 15) {
            const float* Ap2 = Ap + (kt + 1) * 32;
            const float* Bp2 = Bp + (kt + 1) * 32;
#pragma unroll
            for (int i = 0; i < 4; i++) apf[i] = *(const float4*)(Ap2 + (size_t)(32 * i) * H);
#pragma unroll
            for (int i = 0; i < 2; i++) bpf[i] = *(const float4*)(Bp2 + (size_t)(32 * i) * H);
        }
#pragma unroll
        for (int k8 = 0; k8 < 4; k8++) {
            const int kk = k8 * 8 + tig;
            uint32_t a[2][4];
#pragma unroll
            for (int mi = 0; mi < 2; mi++) {
                const int r0 = wm + mi * 16;
                a[mi][0] = __float_as_uint(As[r0 + g][kk]);
                a[mi][1] = __float_as_uint(As[r0 + g + 8][kk]);
                a[mi][2] = __float_as_uint(As[r0 + g][kk + 4]);
                a[mi][3] = __float_as_uint(As[r0 + g + 8][kk + 4]);
            }
#pragma unroll
            for (int ni = 0; ni < 4; ni++) {
                uint32_t bb[2];
                const int nr = wn + ni * 8 + g;
                bb[0] = __float_as_uint(Bs[nr][kk]);
                bb[1] = __float_as_uint(Bs[nr][kk + 4]);
#pragma unroll
                for (int mi = 0; mi < 2; mi++) mma_tf32(c[mi][ni], a[mi], bb);
            }
        }
        __syncthreads();
    }
#pragma unroll
    for (int mi = 0; mi < 2; mi++) {
        const size_t r0 = row0 + wm + mi * 16 + g;
#pragma unroll
        for (int ni = 0; ni < 4; ni++) {
            const int cc = col0 + wn + ni * 8 + 2 * tig;
            const float b0 = b_ih[cc], b1 = b_ih[cc + 1];
            float* C0 = g_gi + r0 * H3 + cc;
            float* C1 = g_gi + (r0 + 8) * H3 + cc;
            C0[0] = c[mi][ni][0] + b0; C0[1] = c[mi][ni][1] + b1;
            C1[0] = c[mi][ni][2] + b0; C1[1] = c[mi][ni][3] + b1;
        }
    }
}

// ---------------------------------------------------------------------------
// Persistent GRU kernel v3.
// 64 CTAs x 256 threads (8 warps). Warp w: band = w>>2 (64 rows), ks = w&3
// (K-slice of 128). Weights register-resident (96 regs/warp, loaded once).
// h streamed per band in 16-row x 512-float stages (one m16 tile each) via
// cp.async double buffer + named barriers. Cross-K reduction through SMEM;
// gates computed by all 256 threads.
// ---------------------------------------------------------------------------
constexpr int GCTAS = 64;
constexpr int HLD = 516;                       // stage row stride (floats)
constexpr int STG_FLOATS = 16 * HLD;           // 8256
constexpr int HS_FLOATS = 2 * 2 * STG_FLOATS;  // 2 bands x 2 bufs
constexpr int RLD = 28;                        // Red row stride (floats)
constexpr int GRU_SMEM = (HS_FLOATS + 4 * 128 * RLD) * 4;  // 189,440 B

__device__ __forceinline__ void issue_stage(float* Hband, int buf, const float* hcur,
                                            int band, int s, int lt) {
    float* dst = Hband + buf * STG_FLOATS + (lt >> 3) * HLD + (lt & 7) * 4;
    const float* src = hcur + (band * 64 + s * 16 + (lt >> 3)) * H + (lt & 7) * 4;
#pragma unroll
    for (int i = 0; i < 16; i++) cp16(dst + i * 32, src + i * 32);
    asm volatile("cp.async.commit_group;" ::: "memory");
}

__global__ void __launch_bounds__(256, 1) gru_kernel(const float* __restrict__ w_hh,
                                                     const float* __restrict__ b_hh) {
    extern __shared__ float sm[];
    const int tid = threadIdx.x, warp = tid >> 5, lane = tid & 31;
    const int g = lane >> 2, tig = lane & 3;
    const int band = warp >> 2, ks = warp & 3;
    const int j0 = blockIdx.x * 8;
    const int lt = tid & 127;
    float* Hband = sm + band * (2 * STG_FLOATS);
    float* Red = sm + HS_FLOATS;

    // Register-resident weight fragments: b[k=tig(+4)][n=g] for this warp's
    // K-slice. Loaded once; raw fp32 bits (HMMA truncates to tf32).
    uint32_t breg[16][3][2];
#pragma unroll
    for (int nb = 0; nb < 3; nb++) {
        const float* wp = w_hh + (size_t)(nb * H + j0 + g) * H + ks * 128 + tig;
#pragma unroll
        for (int k8 = 0; k8 < 16; k8++) {
            breg[k8][nb][0] = __float_as_uint(wp[k8 * 8]);
            breg[k8][nb][1] = __float_as_uint(wp[k8 * 8 + 4]);
        }
    }

    // Gate-side assignment: thread -> row gr_, dims j0+dq..j0+dq+3
    const int gr_ = tid >> 1;
    const int dq = (tid & 1) * 4;
    const float4 bh0 = *(const float4*)(b_hh + j0 + dq);
    const float4 bh1 = *(const float4*)(b_hh + H + j0 + dq);
    const float4 bh2 = *(const float4*)(b_hh + 2 * H + j0 + dq);

    int p = 0;
    for (int t = 0; t < L; t++) {
        const float* hcur = g_h[p];
        float* hnxt = g_h[p ^ 1];

        // Prefetch this step's gi + h_old for the gate phase
        const float* gi_t = g_gi + (size_t)t * (B * H3) + (size_t)gr_ * H3;
        const float4 gi0 = *(const float4*)(gi_t + j0 + dq);
        const float4 gi1 = *(const float4*)(gi_t + H + j0 + dq);
        const float4 gi2 = *(const float4*)(gi_t + 2 * H + j0 + dq);
        const float4 hq  = *(const float4*)(hcur + gr_ * H + j0 + dq);

        // Stage pipeline: 4 stages of 16 rows, double-buffered per band
        issue_stage(Hband, 0, hcur, band, 0, lt);

        float c[4][3][4] = {};
#pragma unroll
        for (int s = 0; s < 4; s++) {
            asm volatile("cp.async.wait_group 0;" ::: "memory");
            asm volatile("bar.sync %0, %1;" :: "r"(band + 1), "r"(128) : "memory");
            if (s < 3) issue_stage(Hband, (s + 1) & 1, hcur, band, s + 1, lt);
            const float* Hb = Hband + (s & 1) * STG_FLOATS + g * HLD + ks * 128 + tig;
#pragma unroll
            for (int k8 = 0; k8 < 16; k8++) {
                uint32_t a[4];
                a[0] = __float_as_uint(Hb[k8 * 8]);
                a[1] = __float_as_uint(Hb[8 * HLD + k8 * 8]);
                a[2] = __float_as_uint(Hb[k8 * 8 + 4]);
                a[3] = __float_as_uint(Hb[8 * HLD + k8 * 8 + 4]);
                mma_tf32(c[s][0], a, breg[k8][0]);
                mma_tf32(c[s][1], a, breg[k8][1]);
                mma_tf32(c[s][2], a, breg[k8][2]);
            }
        }

        // Dump partials: Red[ks][row][nb*8 + 2*tig (+1)]
#pragma unroll
        for (int s = 0; s < 4; s++) {
            const int row = band * 64 + s * 16 + g;
            float* r0 = Red + ks * (128 * RLD) + row * RLD + 2 * tig;
#pragma unroll
            for (int nb = 0; nb < 3; nb++) {
                float2 v0 = make_float2(c[s][nb][0], c[s][nb][1]);
                float2 v1 = make_float2(c[s][nb][2], c[s][nb][3]);
                *(float2*)(r0 + nb * 8) = v0;
                *(float2*)(r0 + nb * 8 + 8 * RLD) = v1;
            }
        }
        __syncthreads();

        // Gates: sum 4 K-partials, add biases, nonlinearity, write h
        float4 s0 = make_float4(0.f, 0.f, 0.f, 0.f), s1 = s0, s2 = s0;
#pragma unroll
        for (int k = 0; k < 4; k++) {
            const float* rp = Red + k * (128 * RLD) + gr_ * RLD + dq;
            const float4 a0 = *(const float4*)(rp);
            const float4 a1 = *(const float4*)(rp + 8);
            const float4 a2 = *(const float4*)(rp + 16);
            s0.x += a0.x; s0.y += a0.y; s0.z += a0.z; s0.w += a0.w;
            s1.x += a1.x; s1.y += a1.y; s1.z += a1.z; s1.w += a1.w;
            s2.x += a2.x; s2.y += a2.y; s2.z += a2.z; s2.w += a2.w;
        }
        float4 hn;
        {
            const float ghr[4] = {s0.x + bh0.x, s0.y + bh0.y, s0.z + bh0.z, s0.w + bh0.w};
            const float ghz[4] = {s1.x + bh1.x, s1.y + bh1.y, s1.z + bh1.z, s1.w + bh1.w};
            const float ghn[4] = {s2.x + bh2.x, s2.y + bh2.y, s2.z + bh2.z, s2.w + bh2.w};
            const float gia[4] = {gi0.x, gi0.y, gi0.z, gi0.w};
            const float gib[4] = {gi1.x, gi1.y, gi1.z, gi1.w};
            const float gic[4] = {gi2.x, gi2.y, gi2.z, gi2.w};
            const float ho[4] = {hq.x, hq.y, hq.z, hq.w};
            float out[4];
#pragma unroll
            for (int q = 0; q < 4; q++) {
                const float r = 1.0f / (1.0f + __expf(-(gia[q] + ghr[q])));
                const float z = 1.0f / (1.0f + __expf(-(gib[q] + ghz[q])));
                const float n = tanhf(gic[q] + r * ghn[q]);
                out[q] = (1.0f - z) * n + z * ho[q];
            }
            hn = make_float4(out[0], out[1], out[2], out[3]);
        }
        *(float4*)(hnxt + gr_ * H + j0 + dq) = hn;

        // Grid barrier
        __threadfence();
        __syncthreads();
        if (tid == 0) {
            const unsigned target = (unsigned)(t + 1);
            if (atomicAdd(&g_bar_count, 1u) == GCTAS - 1) {
                atomicExch(&g_bar_count, 0u);
                __threadfence();
                atomicExch(&g_bar_gen, target);
            } else {
                while (*(volatile unsigned*)&g_bar_gen < target) {}
            }
        }
        __syncthreads();
        p ^= 1;
    }
}

// ---------------------------------------------------------------------------
// Classifier
// ---------------------------------------------------------------------------
__global__ void classifier_kernel(const float* __restrict__ cls_w,
                                  const float* __restrict__ cls_b,
                                  float* __restrict__ out) {
    const int b = blockIdx.x / C;
    const int cc = blockIdx.x % C;
    const float* h = g_h[0] + b * H;
    const float* w = cls_w + cc * H;
    float s = 0.0f;
    for (int k = threadIdx.x; k < H; k += 64) s += h[k] * w[k];
#pragma unroll
    for (int o = 16; o > 0; o >>= 1) s += __shfl_down_sync(0xffffffffu, s, o);
    __shared__ float red[2];
    if ((threadIdx.x & 31) == 0) red[threadIdx.x >> 5] = s;
    __syncthreads();
    if (threadIdx.x == 0) out[b * C + cc] = red[0] + red[1] + cls_b[cc];
}

// ---------------------------------------------------------------------------
// Launch
// ---------------------------------------------------------------------------
extern "C" void kernel_launch(void* const* d_in, const int* in_sizes, int n_in,
                              void* d_out, int out_size) {
    const int*   x      = (const int*)d_in[0];
    const float* conv_w = (const float*)d_in[1];
    const float* conv_b = (const float*)d_in[2];
    const float* w_ih   = (const float*)d_in[3];
    const float* w_hh   = (const float*)d_in[4];
    const float* b_ih   = (const float*)d_in[5];
    const float* b_hh   = (const float*)d_in[6];
    const float* cls_w  = (const float*)d_in[7];
    const float* cls_b  = (const float*)d_in[8];
    float* out = (float*)d_out;

    cudaFuncSetAttribute(gru_kernel, cudaFuncAttributeMaxDynamicSharedMemorySize, GRU_SMEM);

    init_kernel<<<512, 256>>>();
    transpose_kernel<<<(H * V * 3 + 255) / 256, 256>>>(conv_w);
    embed_kernel<<<NROW, 128>>>(x, conv_b);
    gi_gemm_kernel<<<dim3(H3 / 64, NROW / 128), 256>>>(w_ih, b_ih);
    gru_kernel<<<GCTAS, 256, GRU_SMEM>>>(w_hh, b_hh);
    classifier_kernel<<<B * C, 64>>>(cls_w, cls_b, out);
}

// round 6
// speedup vs baseline: 1.5580x; 1.5137x over previous
#include <cuda_runtime.h>
#include <cuda_bf16.h>
#include <cstdint>

// Problem constants
constexpr int B = 128, L = 1024, V = 512, H = 512, C = 20;
constexpr int H3 = 3 * H;          // 1536
constexpr int NROW = L * B;        // 131072

// ---------------------------------------------------------------------------
// Device scratch
// ---------------------------------------------------------------------------
__device__ float g_T[3][V][H];                         // transposed conv weights
__device__ __nv_bfloat16 g_yB[(size_t)NROW * H];       // conv output (bf16)
__device__ __nv_bfloat16 g_wihB[(size_t)H3 * H];       // w_ih in bf16
__device__ float g_gi[(size_t)NROW * H3];              // input-side gate preacts
__device__ float g_h[2][B * H];                        // double-buffered hidden state
constexpr int NGRP = 8, GRP = 16;                      // 8 row-groups x 16 CTAs
__device__ unsigned g_gcnt[NGRP];
__device__ unsigned g_ggen[NGRP];

// ---------------------------------------------------------------------------
// Helpers
// ---------------------------------------------------------------------------
__device__ __forceinline__ void mma_tf32(float c[4], const uint32_t a[4], const uint32_t b[2]) {
    asm volatile(
        "mma.sync.aligned.m16n8k8.row.col.f32.tf32.tf32.f32 "
        "{%0,%1,%2,%3}, {%4,%5,%6,%7}, {%8,%9}, {%0,%1,%2,%3};\n"
        : "+f"(c[0]), "+f"(c[1]), "+f"(c[2]), "+f"(c[3])
        : "r"(a[0]), "r"(a[1]), "r"(a[2]), "r"(a[3]), "r"(b[0]), "r"(b[1]));
}

__device__ __forceinline__ void mma_bf16(float c[4], const uint32_t a[4], const uint32_t b[2]) {
    asm volatile(
        "mma.sync.aligned.m16n8k16.row.col.f32.bf16.bf16.f32 "
        "{%0,%1,%2,%3}, {%4,%5,%6,%7}, {%8,%9}, {%0,%1,%2,%3};\n"
        : "+f"(c[0]), "+f"(c[1]), "+f"(c[2]), "+f"(c[3])
        : "r"(a[0]), "r"(a[1]), "r"(a[2]), "r"(a[3]), "r"(b[0]), "r"(b[1]));
}

__device__ __forceinline__ void cp16(void* dst_smem, const void* src) {
    uint32_t d = (uint32_t)__cvta_generic_to_shared(dst_smem);
    asm volatile("cp.async.cg.shared.global [%0], [%1], 16;" :: "r"(d), "l"(src));
}
#define CP_COMMIT()  asm volatile("cp.async.commit_group;" ::: "memory")
#define CP_WAIT0()   asm volatile("cp.async.wait_group 0;" ::: "memory")

// ---------------------------------------------------------------------------
// Init (runs every launch — graph replays)
// ---------------------------------------------------------------------------
__global__ void init_kernel() {
    const int i = blockIdx.x * blockDim.x + threadIdx.x;
    if (i < 2 * B * H) ((float*)g_h)[i] = 0.0f;
    if (i < NGRP) { g_gcnt[i] = 0u; g_ggen[i] = 0u; }
}

// ---------------------------------------------------------------------------
// Prep: transpose conv_w -> g_T ; convert w_ih -> bf16
// (H*V*3 == H3*H == 786432, one grid covers both)
// ---------------------------------------------------------------------------
__global__ void prep_kernel(const float* __restrict__ conv_w, const float* __restrict__ w_ih) {
    const int idx = blockIdx.x * blockDim.x + threadIdx.x;
    if (idx < H * V * 3) {
        const int k = idx % 3;
        const int v = (idx / 3) % V;
        const int h = idx / (3 * V);
        g_T[k][v][h] = conv_w[idx];
        g_wihB[idx] = __float2bfloat16_rn(w_ih[idx]);
    }
}

// ---------------------------------------------------------------------------
// Embedding "conv" -> bf16 y
// ---------------------------------------------------------------------------
__global__ void embed_kernel(const int* __restrict__ x, const float* __restrict__ conv_b) {
    const int n = blockIdx.x;      // n = t*B + b
    const int t = n >> 7;
    const int b = n & 127;
    const int x0 = x[b * L + t];
    const int xm = (t > 0) ? x[b * L + t - 1] : -1;
    const int xp = (t < L - 1) ? x[b * L + t + 1] : -1;
    const int hb = threadIdx.x * 4;

    float4 acc = *(const float4*)(conv_b + hb);
    {
        const float4 e = *(const float4*)(&g_T[1][x0][hb]);
        acc.x += e.x; acc.y += e.y; acc.z += e.z; acc.w += e.w;
    }
    if (xm >= 0) {
        const float4 e = *(const float4*)(&g_T[0][xm][hb]);
        acc.x += e.x; acc.y += e.y; acc.z += e.z; acc.w += e.w;
    }
    if (xp >= 0) {
        const float4 e = *(const float4*)(&g_T[2][xp][hb]);
        acc.x += e.x; acc.y += e.y; acc.z += e.z; acc.w += e.w;
    }
    __nv_bfloat162 p0, p1;
    p0.x = __float2bfloat16_rn(fmaxf(acc.x, 0.0f));
    p0.y = __float2bfloat16_rn(fmaxf(acc.y, 0.0f));
    p1.x = __float2bfloat16_rn(fmaxf(acc.z, 0.0f));
    p1.y = __float2bfloat16_rn(fmaxf(acc.w, 0.0f));
    *(__nv_bfloat162*)(g_yB + (size_t)n * H + hb) = p0;
    *(__nv_bfloat162*)(g_yB + (size_t)n * H + hb + 2) = p1;
}

// ---------------------------------------------------------------------------
// gi = y @ w_ih^T + b_ih  -- bf16 m16n8k16 NT GEMM, M=131072 N=1536 K=512
// CTA tile 128x64, 8 warps (4x2), warp tile 32x32
// ---------------------------------------------------------------------------
__global__ void __launch_bounds__(256) gi_gemm_kernel(const float* __restrict__ b_ih) {
    __shared__ uint32_t AsW[128][20];   // 128 rows x 16 words (32 halfs) + pad
    __shared__ uint32_t BsW[64][20];
    const int tid = threadIdx.x;
    const int warp = tid >> 5, lane = tid & 31;
    const int g = lane >> 2, tig = lane & 3;
    const int wm = (warp >> 1) * 32;
    const int wn = (warp & 1) * 32;
    const size_t row0 = (size_t)blockIdx.y * 128;
    const int col0 = blockIdx.x * 64;

    float c[2][4][4];
#pragma unroll
    for (int mi = 0; mi < 2; mi++)
#pragma unroll
        for (int ni = 0; ni < 4; ni++)
#pragma unroll
            for (int q = 0; q < 4; q++) c[mi][ni][q] = 0.0f;

    // Producers: A: thread -> row tid>>1, half-part tid&1 (16 halfs = 2 uint4)
    //            B: thread(<256) -> row tid>>2, quarter tid&3 (8 halfs = 1 uint4)
    const int pr = tid >> 1, pp = tid & 1;
    const int br = tid >> 2, bp = tid & 3;
    const uint4* ApRow = (const uint4*)(g_yB + (row0 + pr) * H);
    const uint4* BpRow = (const uint4*)(g_wihB + (size_t)(col0 + br) * H);

    uint4 af0 = ApRow[pp * 2], af1 = ApRow[pp * 2 + 1];
    uint4 bf = BpRow[bp];

    for (int kt = 0; kt < 16; kt++) {
        *(uint4*)&AsW[pr][pp * 8] = af0;
        *(uint4*)&AsW[pr][pp * 8 + 4] = af1;
        *(uint4*)&BsW[br][bp * 4] = bf;
        __syncthreads();
        if (kt < 15) {
            af0 = ApRow[(kt + 1) * 4 + pp * 2];
            af1 = ApRow[(kt + 1) * 4 + pp * 2 + 1];
            bf = BpRow[(kt + 1) * 4 + bp];
        }
#pragma unroll
        for (int ks = 0; ks < 2; ks++) {
            const int kw = ks * 8 + tig;
            uint32_t a[2][4];
#pragma unroll
            for (int mi = 0; mi < 2; mi++) {
                const int r0 = wm + mi * 16;
                a[mi][0] = AsW[r0 + g][kw];
                a[mi][1] = AsW[r0 + g + 8][kw];
                a[mi][2] = AsW[r0 + g][kw + 4];
                a[mi][3] = AsW[r0 + g + 8][kw + 4];
            }
#pragma unroll
            for (int ni = 0; ni < 4; ni++) {
                uint32_t bb[2];
                const int nr = wn + ni * 8 + g;
                bb[0] = BsW[nr][kw];
                bb[1] = BsW[nr][kw + 4];
#pragma unroll
                for (int mi = 0; mi < 2; mi++) mma_bf16(c[mi][ni], a[mi], bb);
            }
        }
        __syncthreads();
    }
#pragma unroll
    for (int mi = 0; mi < 2; mi++) {
        const size_t r0 = row0 + wm + mi * 16 + g;
#pragma unroll
        for (int ni = 0; ni < 4; ni++) {
            const int cc = col0 + wn + ni * 8 + 2 * tig;
            const float b0 = b_ih[cc], b1 = b_ih[cc + 1];
            float* C0 = g_gi + r0 * H3 + cc;
            float* C1 = g_gi + (r0 + 8) * H3 + cc;
            C0[0] = c[mi][ni][0] + b0; C0[1] = c[mi][ni][1] + b1;
            C1[0] = c[mi][ni][2] + b0; C1[1] = c[mi][ni][3] + b1;
        }
    }
}

// ---------------------------------------------------------------------------
// Persistent GRU kernel v5: 128 CTAs x 256 threads.
// CTA (rg = bid>>4, dg = bid&15): rows rg*16..+15, hidden dims dg*32..+31.
// N = 96 cols (3 gates x 32 dims), M = 16, K = 512. Only the 16 CTAs of a
// row-group synchronize (independent groups => no chip-wide barrier).
// w_hh slice resident in SMEM (196 KB); h rows streamed via cp.async (32 KB).
// Warp w: nt = w>>1 owns cols nt*24..+23, kh = w&1 owns K-half; cross-K
// reduction + gates via Red (aliased into the A tile).
// ---------------------------------------------------------------------------
constexpr int WCLD = 516;                       // Wc row stride (floats)
constexpr int ALD = 516;                        // A row stride (floats)
constexpr int A_OFF = 96 * WCLD;                // floats
constexpr int GRU_SMEM = (96 * WCLD + 16 * ALD) * 4;   // 231,168 B
constexpr int RLD = 100;                        // Red row stride (floats)

__global__ void __launch_bounds__(256, 1) gru_kernel(const float* __restrict__ w_hh,
                                                     const float* __restrict__ b_hh) {
    extern __shared__ float sm[];
    float* Wc = sm;                 // [96][WCLD]
    float* Ah = sm + A_OFF;         // [16][ALD]
    float* Red = Ah;                // aliased: [16][RLD] (used after mma reads)

    const int tid = threadIdx.x;
    const int warp = tid >> 5, lane = tid & 31;
    const int g = lane >> 2, tig = lane & 3;
    const int nt = warp >> 1, kh = warp & 1;
    const int rg = blockIdx.x >> 4, dg = blockIdx.x & 15;

    // Load w_hh slice: Wc row n = gate*32 + jj  <->  w_hh row gate*H + dg*32 + jj
    for (int i = tid; i < 96 * 512; i += 256) {
        const int n = i >> 9, k = i & 511;
        Wc[n * WCLD + k] = w_hh[(size_t)((n >> 5) * H + dg * 32 + (n & 31)) * H + k];
    }

    // Gate-phase assignment: thread -> row (tid>>4), dim pair (tid&15)*2
    const int row_e = tid >> 4;
    const int j2 = (tid & 15) * 2;
    const int grow_e = rg * 16 + row_e;
    const float2 bh0 = *(const float2*)(b_hh + dg * 32 + j2);
    const float2 bh1 = *(const float2*)(b_hh + H + dg * 32 + j2);
    const float2 bh2 = *(const float2*)(b_hh + 2 * H + dg * 32 + j2);

    // cp.async assignment: thread -> row (tid>>4), 32-float segment (tid&15)
    const int cr = tid >> 4, cs = (tid & 15) * 32;

    // Mainloop bases
    const float* W0 = Wc + (nt * 24 + g) * WCLD + kh * 256;
    const float* W1 = W0 + 8 * WCLD;
    const float* W2 = W0 + 16 * WCLD;
    const float* A0 = Ah + g * ALD + kh * 256;

    __syncthreads();

    int p = 0;
    for (int t = 0; t < L; t++) {
        const float* hcur = g_h[p];
        float* hnxt = g_h[p ^ 1];

        // Stream this group's 16 h rows into SMEM
        {
            const float* src = hcur + (rg * 16 + cr) * H + cs;
            float* dst = Ah + cr * ALD + cs;
#pragma unroll
            for (int i = 0; i < 8; i++) cp16(dst + i * 4, src + i * 4);
            CP_COMMIT();
        }

        // Prefetch gi + h_old for the gate phase (overlaps cp + mma)
        const float* gip = g_gi + (size_t)t * (B * H3) + (size_t)grow_e * H3 + dg * 32 + j2;
        const float2 gr2 = *(const float2*)(gip);
        const float2 gz2 = *(const float2*)(gip + H);
        const float2 gn2 = *(const float2*)(gip + 2 * H);
        const float2 ho2 = *(const float2*)(hcur + grow_e * H + dg * 32 + j2);

        CP_WAIT0();
        __syncthreads();

        float c0[4] = {}, c1[4] = {}, c2[4] = {};
#pragma unroll 8
        for (int k8 = 0; k8 < 32; k8++) {
            const int k = k8 * 8 + tig;
            uint32_t a[4];
            a[0] = __float_as_uint(A0[k]);
            a[1] = __float_as_uint(A0[8 * ALD + k]);
            a[2] = __float_as_uint(A0[k + 4]);
            a[3] = __float_as_uint(A0[8 * ALD + k + 4]);
            uint32_t b[2];
            b[0] = __float_as_uint(W0[k]); b[1] = __float_as_uint(W0[k + 4]);
            mma_tf32(c0, a, b);
            b[0] = __float_as_uint(W1[k]); b[1] = __float_as_uint(W1[k + 4]);
            mma_tf32(c1, a, b);
            b[0] = __float_as_uint(W2[k]); b[1] = __float_as_uint(W2[k + 4]);
            mma_tf32(c2, a, b);
        }
        __syncthreads();   // all mma reads of Ah done -> Red may overwrite

        // Cross-K reduction through Red
        const int n0 = nt * 24 + 2 * tig;
        if (kh == 0) {
            *(float2*)&Red[g * RLD + n0]            = make_float2(c0[0], c0[1]);
            *(float2*)&Red[(g + 8) * RLD + n0]      = make_float2(c0[2], c0[3]);
            *(float2*)&Red[g * RLD + n0 + 8]        = make_float2(c1[0], c1[1]);
            *(float2*)&Red[(g + 8) * RLD + n0 + 8]  = make_float2(c1[2], c1[3]);
            *(float2*)&Red[g * RLD + n0 + 16]       = make_float2(c2[0], c2[1]);
            *(float2*)&Red[(g + 8) * RLD + n0 + 16] = make_float2(c2[2], c2[3]);
        }
        __syncthreads();
        if (kh == 1) {
            float2* p0 = (float2*)&Red[g * RLD + n0];
            float2* p1 = (float2*)&Red[(g + 8) * RLD + n0];
            float2 v;
            v = p0[0]; v.x += c0[0]; v.y += c0[1]; p0[0] = v;
            v = p1[0]; v.x += c0[2]; v.y += c0[3]; p1[0] = v;
            v = p0[4]; v.x += c1[0]; v.y += c1[1]; p0[4] = v;
            v = p1[4]; v.x += c1[2]; v.y += c1[3]; p1[4] = v;
            v = p0[8]; v.x += c2[0]; v.y += c2[1]; p0[8] = v;
            v = p1[8]; v.x += c2[2]; v.y += c2[3]; p1[8] = v;
        }
        __syncthreads();

        // Gates: thread owns (row_e, dims j2, j2+1)
        {
            const float2 sr = *(const float2*)&Red[row_e * RLD + j2];
            const float2 sz = *(const float2*)&Red[row_e * RLD + 32 + j2];
            const float2 sn = *(const float2*)&Red[row_e * RLD + 64 + j2];
            const float r0 = 1.0f / (1.0f + __expf(-(gr2.x + sr.x + bh0.x)));
            const float r1 = 1.0f / (1.0f + __expf(-(gr2.y + sr.y + bh0.y)));
            const float z0 = 1.0f / (1.0f + __expf(-(gz2.x + sz.x + bh1.x)));
            const float z1 = 1.0f / (1.0f + __expf(-(gz2.y + sz.y + bh1.y)));
            const float n0v = tanhf(gn2.x + r0 * (sn.x + bh2.x));
            const float n1v = tanhf(gn2.y + r1 * (sn.y + bh2.y));
            float2 hn;
            hn.x = (1.0f - z0) * n0v + z0 * ho2.x;
            hn.y = (1.0f - z1) * n1v + z1 * ho2.y;
            *(float2*)(hnxt + grow_e * H + dg * 32 + j2) = hn;
        }

        // Row-group barrier (16 CTAs)
        __threadfence();
        __syncthreads();
        if (tid == 0) {
            const unsigned target = (unsigned)(t + 1);
            if (atomicAdd(&g_gcnt[rg], 1u) == GRP - 1) {
                atomicExch(&g_gcnt[rg], 0u);
                __threadfence();
                atomicExch(&g_ggen[rg], target);
            } else {
                while (*(volatile unsigned*)&g_ggen[rg] < target) {}
            }
        }
        __syncthreads();
        p ^= 1;
    }
}

// ---------------------------------------------------------------------------
// Classifier
// ---------------------------------------------------------------------------
__global__ void classifier_kernel(const float* __restrict__ cls_w,
                                  const float* __restrict__ cls_b,
                                  float* __restrict__ out) {
    const int b = blockIdx.x / C;
    const int cc = blockIdx.x % C;
    const float* h = g_h[0] + b * H;
    const float* w = cls_w + cc * H;
    float s = 0.0f;
    for (int k = threadIdx.x; k < H; k += 64) s += h[k] * w[k];
#pragma unroll
    for (int o = 16; o > 0; o >>= 1) s += __shfl_down_sync(0xffffffffu, s, o);
    __shared__ float red[2];
    if ((threadIdx.x & 31) == 0) red[threadIdx.x >> 5] = s;
    __syncthreads();
    if (threadIdx.x == 0) out[b * C + cc] = red[0] + red[1] + cls_b[cc];
}

// ---------------------------------------------------------------------------
// Launch
// ---------------------------------------------------------------------------
extern "C" void kernel_launch(void* const* d_in, const int* in_sizes, int n_in,
                              void* d_out, int out_size) {
    const int*   x      = (const int*)d_in[0];
    const float* conv_w = (const float*)d_in[1];
    const float* conv_b = (const float*)d_in[2];
    const float* w_ih   = (const float*)d_in[3];
    const float* w_hh   = (const float*)d_in[4];
    const float* b_ih   = (const float*)d_in[5];
    const float* b_hh   = (const float*)d_in[6];
    const float* cls_w  = (const float*)d_in[7];
    const float* cls_b  = (const float*)d_in[8];
    float* out = (float*)d_out;

    cudaFuncSetAttribute(gru_kernel, cudaFuncAttributeMaxDynamicSharedMemorySize, GRU_SMEM);

    init_kernel<<<512, 256>>>();
    prep_kernel<<<(H * V * 3 + 255) / 256, 256>>>(conv_w, w_ih);
    embed_kernel<<<NROW, 128>>>(x, conv_b);
    gi_gemm_kernel<<<dim3(H3 / 64, NROW / 128), 256>>>(b_ih);
    gru_kernel<<<NGRP * GRP, 256, GRU_SMEM>>>(w_hh, b_hh);
    classifier_kernel<<<B * C, 64>>>(cls_w, cls_b, out);
}

// round 7
// speedup vs baseline: 1.8491x; 1.1868x over previous
#include <cuda_runtime.h>
#include <cuda_bf16.h>
#include <cstdint>

// Problem constants
constexpr int B = 128, L = 1024, V = 512, H = 512, C = 20;
constexpr int H3 = 3 * H;          // 1536
constexpr int NROW = L * B;        // 131072

// ---------------------------------------------------------------------------
// Device scratch
// ---------------------------------------------------------------------------
__device__ float g_T[3][V][H];                         // transposed conv weights
__device__ __nv_bfloat16 g_yB[(size_t)NROW * H];       // conv output (bf16)
__device__ __nv_bfloat16 g_wihB[(size_t)H3 * H];       // w_ih in bf16
__device__ float g_gi[(size_t)NROW * H3];              // input-side gate preacts
__device__ float g_h[2][B * H];                        // hidden state (fp32, exact)
__device__ __nv_bfloat16 g_hB[2][B * H];               // hidden state mirror (bf16, mma A)
constexpr int NGRP = 8, GRP = 16;                      // 8 row-groups x 16 CTAs
__device__ unsigned g_gcnt[NGRP];
__device__ unsigned g_ggen[NGRP];

// ---------------------------------------------------------------------------
// Helpers
// ---------------------------------------------------------------------------
__device__ __forceinline__ void mma_bf16(float c[4], const uint32_t a[4], const uint32_t b[2]) {
    asm volatile(
        "mma.sync.aligned.m16n8k16.row.col.f32.bf16.bf16.f32 "
        "{%0,%1,%2,%3}, {%4,%5,%6,%7}, {%8,%9}, {%0,%1,%2,%3};\n"
        : "+f"(c[0]), "+f"(c[1]), "+f"(c[2]), "+f"(c[3])
        : "r"(a[0]), "r"(a[1]), "r"(a[2]), "r"(a[3]), "r"(b[0]), "r"(b[1]));
}

__device__ __forceinline__ void cp16(void* dst_smem, const void* src) {
    uint32_t d = (uint32_t)__cvta_generic_to_shared(dst_smem);
    asm volatile("cp.async.cg.shared.global [%0], [%1], 16;" :: "r"(d), "l"(src));
}
#define CP_COMMIT()  asm volatile("cp.async.commit_group;" ::: "memory")
#define CP_WAIT0()   asm volatile("cp.async.wait_group 0;" ::: "memory")

// ---------------------------------------------------------------------------
// Init (runs every launch — graph replays)
// ---------------------------------------------------------------------------
__global__ void init_kernel() {
    const int i = blockIdx.x * blockDim.x + threadIdx.x;
    if (i < 2 * B * H) {
        ((float*)g_h)[i] = 0.0f;
        ((__nv_bfloat16*)g_hB)[i] = __float2bfloat16(0.0f);
    }
    if (i < NGRP) { g_gcnt[i] = 0u; g_ggen[i] = 0u; }
}

// ---------------------------------------------------------------------------
// Prep: transpose conv_w -> g_T ; convert w_ih -> bf16
// ---------------------------------------------------------------------------
__global__ void prep_kernel(const float* __restrict__ conv_w, const float* __restrict__ w_ih) {
    const int idx = blockIdx.x * blockDim.x + threadIdx.x;
    if (idx < H * V * 3) {
        const int k = idx % 3;
        const int v = (idx / 3) % V;
        const int h = idx / (3 * V);
        g_T[k][v][h] = conv_w[idx];
        g_wihB[idx] = __float2bfloat16_rn(w_ih[idx]);
    }
}

// ---------------------------------------------------------------------------
// Embedding "conv" -> bf16 y
// ---------------------------------------------------------------------------
__global__ void embed_kernel(const int* __restrict__ x, const float* __restrict__ conv_b) {
    const int n = blockIdx.x;      // n = t*B + b
    const int t = n >> 7;
    const int b = n & 127;
    const int x0 = x[b * L + t];
    const int xm = (t > 0) ? x[b * L + t - 1] : -1;
    const int xp = (t < L - 1) ? x[b * L + t + 1] : -1;
    const int hb = threadIdx.x * 4;

    float4 acc = *(const float4*)(conv_b + hb);
    {
        const float4 e = *(const float4*)(&g_T[1][x0][hb]);
        acc.x += e.x; acc.y += e.y; acc.z += e.z; acc.w += e.w;
    }
    if (xm >= 0) {
        const float4 e = *(const float4*)(&g_T[0][xm][hb]);
        acc.x += e.x; acc.y += e.y; acc.z += e.z; acc.w += e.w;
    }
    if (xp >= 0) {
        const float4 e = *(const float4*)(&g_T[2][xp][hb]);
        acc.x += e.x; acc.y += e.y; acc.z += e.z; acc.w += e.w;
    }
    __nv_bfloat162 p0, p1;
    p0.x = __float2bfloat16_rn(fmaxf(acc.x, 0.0f));
    p0.y = __float2bfloat16_rn(fmaxf(acc.y, 0.0f));
    p1.x = __float2bfloat16_rn(fmaxf(acc.z, 0.0f));
    p1.y = __float2bfloat16_rn(fmaxf(acc.w, 0.0f));
    *(__nv_bfloat162*)(g_yB + (size_t)n * H + hb) = p0;
    *(__nv_bfloat162*)(g_yB + (size_t)n * H + hb + 2) = p1;
}

// ---------------------------------------------------------------------------
// gi = y @ w_ih^T + b_ih  -- bf16 m16n8k16 NT GEMM (unchanged — known working)
// ---------------------------------------------------------------------------
__global__ void __launch_bounds__(256) gi_gemm_kernel(const float* __restrict__ b_ih) {
    __shared__ uint32_t AsW[128][20];
    __shared__ uint32_t BsW[64][20];
    const int tid = threadIdx.x;
    const int warp = tid >> 5, lane = tid & 31;
    const int g = lane >> 2, tig = lane & 3;
    const int wm = (warp >> 1) * 32;
    const int wn = (warp & 1) * 32;
    const size_t row0 = (size_t)blockIdx.y * 128;
    const int col0 = blockIdx.x * 64;

    float c[2][4][4];
#pragma unroll
    for (int mi = 0; mi < 2; mi++)
#pragma unroll
        for (int ni = 0; ni < 4; ni++)
#pragma unroll
            for (int q = 0; q < 4; q++) c[mi][ni][q] = 0.0f;

    const int pr = tid >> 1, pp = tid & 1;
    const int br = tid >> 2, bp = tid & 3;
    const uint4* ApRow = (const uint4*)(g_yB + (row0 + pr) * H);
    const uint4* BpRow = (const uint4*)(g_wihB + (size_t)(col0 + br) * H);

    uint4 af0 = ApRow[pp * 2], af1 = ApRow[pp * 2 + 1];
    uint4 bf = BpRow[bp];

    for (int kt = 0; kt < 16; kt++) {
        *(uint4*)&AsW[pr][pp * 8] = af0;
        *(uint4*)&AsW[pr][pp * 8 + 4] = af1;
        *(uint4*)&BsW[br][bp * 4] = bf;
        __syncthreads();
        if (kt < 15) {
            af0 = ApRow[(kt + 1) * 4 + pp * 2];
            af1 = ApRow[(kt + 1) * 4 + pp * 2 + 1];
            bf = BpRow[(kt + 1) * 4 + bp];
        }
#pragma unroll
        for (int ks = 0; ks < 2; ks++) {
            const int kw = ks * 8 + tig;
            uint32_t a[2][4];
#pragma unroll
            for (int mi = 0; mi < 2; mi++) {
                const int r0 = wm + mi * 16;
                a[mi][0] = AsW[r0 + g][kw];
                a[mi][1] = AsW[r0 + g + 8][kw];
                a[mi][2] = AsW[r0 + g][kw + 4];
                a[mi][3] = AsW[r0 + g + 8][kw + 4];
            }
#pragma unroll
            for (int ni = 0; ni < 4; ni++) {
                uint32_t bb[2];
                const int nr = wn + ni * 8 + g;
                bb[0] = BsW[nr][kw];
                bb[1] = BsW[nr][kw + 4];
#pragma unroll
                for (int mi = 0; mi < 2; mi++) mma_bf16(c[mi][ni], a[mi], bb);
            }
        }
        __syncthreads();
    }
#pragma unroll
    for (int mi = 0; mi < 2; mi++) {
        const size_t r0 = row0 + wm + mi * 16 + g;
#pragma unroll
        for (int ni = 0; ni < 4; ni++) {
            const int cc = col0 + wn + ni * 8 + 2 * tig;
            const float b0 = b_ih[cc], b1 = b_ih[cc + 1];
            float* C0 = g_gi + r0 * H3 + cc;
            float* C1 = g_gi + (r0 + 8) * H3 + cc;
            C0[0] = c[mi][ni][0] + b0; C0[1] = c[mi][ni][1] + b1;
            C1[0] = c[mi][ni][2] + b0; C1[1] = c[mi][ni][3] + b1;
        }
    }
}

// ---------------------------------------------------------------------------
// Persistent GRU kernel v6: bf16 m16n8k16 mainloop.
// 128 CTAs x 256 threads. CTA (rg, dg): rows rg*16..+15, dims dg*32..+31.
// N = 96 (3 gates x 32 dims), M = 16, K = 512. w_hh slice in SMEM as bf16
// (words, stride 260 -> conflict-free). h: fp32 master + bf16 mirror; cp.async
// streams the bf16 mirror (16 KB/step). Warp (nt, kh): cols nt*24..+23,
// K-half kh. 48 bf16 mma/warp/step. Red[2] regions -> one sync in reduction.
// ---------------------------------------------------------------------------
constexpr int WLDW = 260;                        // row stride in words
constexpr int A_OFFW = 96 * WLDW;                // A tile offset (words)
constexpr int GRU_SMEM = (96 * WLDW + 16 * WLDW) * 4;   // 116,480 B
constexpr int RLD = 100;                         // Red row stride (floats)

__global__ void __launch_bounds__(256, 1) gru_kernel(const float* __restrict__ w_hh,
                                                     const float* __restrict__ b_hh) {
    extern __shared__ uint32_t smw[];
    float* Red = (float*)(smw + A_OFFW);          // aliased over A tile

    const int tid = threadIdx.x;
    const int warp = tid >> 5, lane = tid & 31;
    const int g = lane >> 2, tig = lane & 3;
    const int nt = warp >> 1, kh = warp & 1;
    const int rg = blockIdx.x >> 4, dg = blockIdx.x & 15;

    // Load w_hh slice -> bf16 words. Row n = gate*32+jj -> w_hh[(gate*H + dg*32+jj)]
    for (int i = tid; i < 96 * 256; i += 256) {
        const int n = i >> 8, w = i & 255;
        const float* src = w_hh + (size_t)((n >> 5) * H + dg * 32 + (n & 31)) * H + 2 * w;
        __nv_bfloat162 pk;
        pk.x = __float2bfloat16_rn(src[0]);
        pk.y = __float2bfloat16_rn(src[1]);
        smw[n * WLDW + w] = *(const uint32_t*)&pk;
    }

    // Gate-phase assignment: thread -> row (tid>>4), dim pair (tid&15)*2
    const int row_e = tid >> 4;
    const int j2 = (tid & 15) * 2;
    const int grow_e = rg * 16 + row_e;
    const float2 bh0 = *(const float2*)(b_hh + dg * 32 + j2);
    const float2 bh1 = *(const float2*)(b_hh + H + dg * 32 + j2);
    const float2 bh2 = *(const float2*)(b_hh + 2 * H + dg * 32 + j2);

    // cp.async assignment: thread -> row (tid>>4), 16B-chunk group (tid&15)
    const int cr = tid >> 4, seg = tid & 15;

    // Mainloop bases
    const uint32_t* W0 = smw + (nt * 24 + g) * WLDW + kh * 128;
    const uint32_t* W1 = W0 + 8 * WLDW;
    const uint32_t* W2 = W0 + 16 * WLDW;
    const uint32_t* A0 = smw + A_OFFW + g * WLDW + kh * 128;
    const uint32_t* A1 = A0 + 8 * WLDW;

    __syncthreads();

    int p = 0;
    for (int t = 0; t < L; t++) {
        const float* hcur = g_h[p];
        float* hnxt = g_h[p ^ 1];
        const __nv_bfloat16* hcurB = g_hB[p];
        __nv_bfloat16* hnxtB = g_hB[p ^ 1];

        // Stream this group's 16 bf16 h rows into the A tile
        {
            const __nv_bfloat16* src = hcurB + (rg * 16 + cr) * H + seg * 32;
            uint32_t* dst = smw + A_OFFW + cr * WLDW + seg * 16;
#pragma unroll
            for (int i = 0; i < 4; i++) cp16(dst + i * 4, src + i * 8);
            CP_COMMIT();
        }

        // Prefetch gi + h_old (overlaps cp)
        const float* gip = g_gi + (size_t)t * (B * H3) + (size_t)grow_e * H3 + dg * 32 + j2;
        const float2 gr2 = *(const float2*)(gip);
        const float2 gz2 = *(const float2*)(gip + H);
        const float2 gn2 = *(const float2*)(gip + 2 * H);
        const float2 ho2 = *(const float2*)(hcur + grow_e * H + dg * 32 + j2);

        CP_WAIT0();
        __syncthreads();

        float c0[4] = {}, c1[4] = {}, c2[4] = {};
#pragma unroll 8
        for (int ck = 0; ck < 16; ck++) {
            const int base = ck * 8 + tig;
            uint32_t a[4];
            a[0] = A0[base];
            a[1] = A1[base];
            a[2] = A0[base + 4];
            a[3] = A1[base + 4];
            uint32_t b[2];
            b[0] = W0[base]; b[1] = W0[base + 4];
            mma_bf16(c0, a, b);
            b[0] = W1[base]; b[1] = W1[base + 4];
            mma_bf16(c1, a, b);
            b[0] = W2[base]; b[1] = W2[base + 4];
            mma_bf16(c2, a, b);
        }
        __syncthreads();   // all mma reads of A tile done -> Red may overwrite

        // Both K-half warps write partials to their own Red region
        {
            float* Rk = Red + kh * (16 * RLD);
            const int n0 = nt * 24 + 2 * tig;
            *(float2*)&Rk[g * RLD + n0]            = make_float2(c0[0], c0[1]);
            *(float2*)&Rk[(g + 8) * RLD + n0]      = make_float2(c0[2], c0[3]);
            *(float2*)&Rk[g * RLD + n0 + 8]        = make_float2(c1[0], c1[1]);
            *(float2*)&Rk[(g + 8) * RLD + n0 + 8]  = make_float2(c1[2], c1[3]);
            *(float2*)&Rk[g * RLD + n0 + 16]       = make_float2(c2[0], c2[1]);
            *(float2*)&Rk[(g + 8) * RLD + n0 + 16] = make_float2(c2[2], c2[3]);
        }
        __syncthreads();

        // Gates: thread owns (row_e, dims j2, j2+1); sum the two K-halves
        {
            const float* Ra = Red + row_e * RLD;
            const float* Rb = Red + 16 * RLD + row_e * RLD;
            const float2 sr0 = *(const float2*)&Ra[j2],      sr1 = *(const float2*)&Rb[j2];
            const float2 sz0 = *(const float2*)&Ra[32 + j2], sz1 = *(const float2*)&Rb[32 + j2];
            const float2 sn0 = *(const float2*)&Ra[64 + j2], sn1 = *(const float2*)&Rb[64 + j2];
            const float r0 = 1.0f / (1.0f + __expf(-(gr2.x + sr0.x + sr1.x + bh0.x)));
            const float r1 = 1.0f / (1.0f + __expf(-(gr2.y + sr0.y + sr1.y + bh0.y)));
            const float z0 = 1.0f / (1.0f + __expf(-(gz2.x + sz0.x + sz1.x + bh1.x)));
            const float z1 = 1.0f / (1.0f + __expf(-(gz2.y + sz0.y + sz1.y + bh1.y)));
            const float n0v = tanhf(gn2.x + r0 * (sn0.x + sn1.x + bh2.x));
            const float n1v = tanhf(gn2.y + r1 * (sn0.y + sn1.y + bh2.y));
            float2 hn;
            hn.x = (1.0f - z0) * n0v + z0 * ho2.x;
            hn.y = (1.0f - z1) * n1v + z1 * ho2.y;
            *(float2*)(hnxt + grow_e * H + dg * 32 + j2) = hn;
            __nv_bfloat162 hb;
            hb.x = __float2bfloat16_rn(hn.x);
            hb.y = __float2bfloat16_rn(hn.y);
            *(__nv_bfloat162*)(hnxtB + grow_e * H + dg * 32 + j2) = hb;
        }

        // Row-group barrier (16 CTAs)
        __threadfence();
        __syncthreads();
        if (tid == 0) {
            const unsigned target = (unsigned)(t + 1);
            if (atomicAdd(&g_gcnt[rg], 1u) == GRP - 1) {
                atomicExch(&g_gcnt[rg], 0u);
                __threadfence();
                atomicExch(&g_ggen[rg], target);
            } else {
                while (*(volatile unsigned*)&g_ggen[rg] < target) {}
            }
        }
        __syncthreads();
        p ^= 1;
    }
}

// ---------------------------------------------------------------------------
// Classifier
// ---------------------------------------------------------------------------
__global__ void classifier_kernel(const float* __restrict__ cls_w,
                                  const float* __restrict__ cls_b,
                                  float* __restrict__ out) {
    const int b = blockIdx.x / C;
    const int cc = blockIdx.x % C;
    const float* h = g_h[0] + b * H;
    const float* w = cls_w + cc * H;
    float s = 0.0f;
    for (int k = threadIdx.x; k < H; k += 64) s += h[k] * w[k];
#pragma unroll
    for (int o = 16; o > 0; o >>= 1) s += __shfl_down_sync(0xffffffffu, s, o);
    __shared__ float red[2];
    if ((threadIdx.x & 31) == 0) red[threadIdx.x >> 5] = s;
    __syncthreads();
    if (threadIdx.x == 0) out[b * C + cc] = red[0] + red[1] + cls_b[cc];
}

// ---------------------------------------------------------------------------
// Launch
// ---------------------------------------------------------------------------
extern "C" void kernel_launch(void* const* d_in, const int* in_sizes, int n_in,
                              void* d_out, int out_size) {
    const int*   x      = (const int*)d_in[0];
    const float* conv_w = (const float*)d_in[1];
    const float* conv_b = (const float*)d_in[2];
    const float* w_ih   = (const float*)d_in[3];
    const float* w_hh   = (const float*)d_in[4];
    const float* b_ih   = (const float*)d_in[5];
    const float* b_hh   = (const float*)d_in[6];
    const float* cls_w  = (const float*)d_in[7];
    const float* cls_b  = (const float*)d_in[8];
    float* out = (float*)d_out;

    cudaFuncSetAttribute(gru_kernel, cudaFuncAttributeMaxDynamicSharedMemorySize, GRU_SMEM);

    init_kernel<<<512, 256>>>();
    prep_kernel<<<(H * V * 3 + 255) / 256, 256>>>(conv_w, w_ih);
    embed_kernel<<<NROW, 128>>>(x, conv_b);
    gi_gemm_kernel<<<dim3(H3 / 64, NROW / 128), 256>>>(b_ih);
    gru_kernel<<<NGRP * GRP, 256, GRU_SMEM>>>(w_hh, b_hh);
    classifier_kernel<<<B * C, 64>>>(cls_w, cls_b, out);
}

// round 8
// speedup vs baseline: 1.9092x; 1.0325x over previous
#include <cuda_runtime.h>
#include <cuda_bf16.h>
#include <cstdint>

// Problem constants
constexpr int B = 128, L = 1024, V = 512, H = 512, C = 20;
constexpr int NROW = L * B;        // 131072

// ---------------------------------------------------------------------------
// Device scratch
// ---------------------------------------------------------------------------
__device__ float g_T[3][V][H];                         // transposed conv weights
__device__ __nv_bfloat16 g_yB[(size_t)NROW * H];       // conv output (bf16)
__device__ float g_h[2][B * H];                        // hidden state (fp32, exact)
__device__ __nv_bfloat16 g_hB[2][B * H];               // hidden state mirror (bf16)
constexpr int NGRP = 8, GRP = 16;                      // 8 row-groups x 16 dim CTAs
__device__ unsigned g_gcnt[NGRP];
__device__ unsigned g_ggen[NGRP];

// ---------------------------------------------------------------------------
// Helpers
// ---------------------------------------------------------------------------
__device__ __forceinline__ void mma_bf16(float c[4], const uint32_t a[4], const uint32_t b[2]) {
    asm volatile(
        "mma.sync.aligned.m16n8k16.row.col.f32.bf16.bf16.f32 "
        "{%0,%1,%2,%3}, {%4,%5,%6,%7}, {%8,%9}, {%0,%1,%2,%3};\n"
        : "+f"(c[0]), "+f"(c[1]), "+f"(c[2]), "+f"(c[3])
        : "r"(a[0]), "r"(a[1]), "r"(a[2]), "r"(a[3]), "r"(b[0]), "r"(b[1]));
}

__device__ __forceinline__ void cp16(void* dst_smem, const void* src) {
    uint32_t d = (uint32_t)__cvta_generic_to_shared(dst_smem);
    asm volatile("cp.async.cg.shared.global [%0], [%1], 16;" :: "r"(d), "l"(src));
}
#define CP_COMMIT()  asm volatile("cp.async.commit_group;" ::: "memory")
#define CP_WAIT0()   asm volatile("cp.async.wait_group 0;" ::: "memory")

// ---------------------------------------------------------------------------
// Init (runs every launch — graph replays)
// ---------------------------------------------------------------------------
__global__ void init_kernel() {
    const int i = blockIdx.x * blockDim.x + threadIdx.x;
    if (i < 2 * B * H) {
        ((float*)g_h)[i] = 0.0f;
        ((__nv_bfloat16*)g_hB)[i] = __float2bfloat16(0.0f);
    }
    if (i < NGRP) { g_gcnt[i] = 0u; g_ggen[i] = 0u; }
}

// ---------------------------------------------------------------------------
// Prep: transpose conv_w -> g_T
// ---------------------------------------------------------------------------
__global__ void prep_kernel(const float* __restrict__ conv_w) {
    const int idx = blockIdx.x * blockDim.x + threadIdx.x;
    if (idx < H * V * 3) {
        const int k = idx % 3;
        const int v = (idx / 3) % V;
        const int h = idx / (3 * V);
        g_T[k][v][h] = conv_w[idx];
    }
}

// ---------------------------------------------------------------------------
// Embedding "conv" -> bf16 y
// ---------------------------------------------------------------------------
__global__ void embed_kernel(const int* __restrict__ x, const float* __restrict__ conv_b) {
    const int n = blockIdx.x;      // n = t*B + b
    const int t = n >> 7;
    const int b = n & 127;
    const int x0 = x[b * L + t];
    const int xm = (t > 0) ? x[b * L + t - 1] : -1;
    const int xp = (t < L - 1) ? x[b * L + t + 1] : -1;
    const int hb = threadIdx.x * 4;

    float4 acc = *(const float4*)(conv_b + hb);
    {
        const float4 e = *(const float4*)(&g_T[1][x0][hb]);
        acc.x += e.x; acc.y += e.y; acc.z += e.z; acc.w += e.w;
    }
    if (xm >= 0) {
        const float4 e = *(const float4*)(&g_T[0][xm][hb]);
        acc.x += e.x; acc.y += e.y; acc.z += e.z; acc.w += e.w;
    }
    if (xp >= 0) {
        const float4 e = *(const float4*)(&g_T[2][xp][hb]);
        acc.x += e.x; acc.y += e.y; acc.z += e.z; acc.w += e.w;
    }
    __nv_bfloat162 p0, p1;
    p0.x = __float2bfloat16_rn(fmaxf(acc.x, 0.0f));
    p0.y = __float2bfloat16_rn(fmaxf(acc.y, 0.0f));
    p1.x = __float2bfloat16_rn(fmaxf(acc.z, 0.0f));
    p1.y = __float2bfloat16_rn(fmaxf(acc.w, 0.0f));
    *(__nv_bfloat162*)(g_yB + (size_t)n * H + hb) = p0;
    *(__nv_bfloat162*)(g_yB + (size_t)n * H + hb + 2) = p1;
}

// ---------------------------------------------------------------------------
// Fused persistent GRU kernel v7: computes gi AND gh per step.
// 128 CTAs x 256 threads (8 warps: nt=warp>>1 col strip of 24, kh=warp&1
// K-half). Per CTA: rows rg*16..+15, dims dg*32..+31.
//   SMEM (XOR-swizzled, zero padding):
//     [0      .. 24576)  w_ih slice bf16  [96 rows][256 words]
//     [24576  .. 49152)  w_hh slice bf16
//     [49152  .. 53248)  y(t) tile   [16][256]
//     [53248  .. 57344)  h(t) tile   [16][256]   (Red aliased here post-mma)
//   Row n of a weight array: tile tt=n>>3 -> gate tt%3, dims (tt/3)*8+(n&7).
//   XOR swizzle: phys word = w ^ ((row&7)<<2)  -> conflict-free frag reads.
// y(t+1) prefetched into registers during mma, stored post-mma sync.
// r/z: gi+gh accumulated together in-register; n: split (gi_n, gh_n).
// ---------------------------------------------------------------------------
constexpr int WHH_OFF = 96 * 256;            // 24576 words
constexpr int YOFF = 2 * 96 * 256;           // 49152
constexpr int HOFF = YOFF + 4096;            // 53248
constexpr int GRU_SMEM = (HOFF + 4096) * 4;  // 229,376 B
constexpr int RLD = 164;                     // Red row stride (floats)

__global__ void __launch_bounds__(256, 1) gru_kernel(const float* __restrict__ w_ih,
                                                     const float* __restrict__ w_hh,
                                                     const float* __restrict__ b_ih,
                                                     const float* __restrict__ b_hh) {
    extern __shared__ uint32_t smw[];
    float* Red = (float*)(smw + HOFF);       // aliased over h tile

    const int tid = threadIdx.x, warp = tid >> 5, lane = tid & 31;
    const int g = lane >> 2, tig = lane & 3;
    const int nt = warp >> 1, kh = warp & 1;
    const int rg = blockIdx.x >> 4, dg = blockIdx.x & 15;
    const int pr = tid >> 4, ps = tid & 15;  // cp/sts row + 16-word segment

    // Prologue: y(0) via cp.async (independent of weights)
    {
        const __nv_bfloat16* src = g_yB + (size_t)(rg * 16 + pr) * H + ps * 32;
#pragma unroll
        for (int i = 0; i < 4; i++) {
            const int w0 = ps * 16 + 4 * i;
            cp16(smw + YOFF + pr * 256 + (w0 ^ ((pr & 7) << 2)), src + i * 8);
        }
        CP_COMMIT();
    }

    // Weights -> SMEM bf16 with XOR swizzle
    for (int i = tid; i < 2 * 96 * 128; i += 256) {
        const int mat = i / (96 * 128);
        const int rem = i - mat * (96 * 128);
        const int n = rem >> 7, f4 = rem & 127;
        const int tt = n >> 3;
        const int grow = (tt % 3) * H + dg * 32 + (tt / 3) * 8 + (n & 7);
        const float* srcm = mat ? w_hh : w_ih;
        const float4 v = *(const float4*)(srcm + (size_t)grow * H + f4 * 4);
        __nv_bfloat162 q0, q1;
        q0.x = __float2bfloat16_rn(v.x); q0.y = __float2bfloat16_rn(v.y);
        q1.x = __float2bfloat16_rn(v.z); q1.y = __float2bfloat16_rn(v.w);
        const int w0 = (f4 * 2) ^ ((n & 7) << 2);   // pair stays consecutive
        uint2 pk;
        pk.x = *(const uint32_t*)&q0;
        pk.y = *(const uint32_t*)&q1;
        *(uint2*)(smw + mat * WHH_OFF + n * 256 + w0) = pk;
    }

    // Gate-phase setup: thread -> (row_e, dim pair j2)
    const int row_e = tid >> 4;
    const int j2 = (tid & 15) * 2;
    const int grow_e = rg * 16 + row_e;
    const int jg = dg * 32 + j2;
    float2 br2, bz2;
    {
        float2 a = *(const float2*)(b_ih + jg), b = *(const float2*)(b_hh + jg);
        br2 = make_float2(a.x + b.x, a.y + b.y);
        a = *(const float2*)(b_ih + H + jg); b = *(const float2*)(b_hh + H + jg);
        bz2 = make_float2(a.x + b.x, a.y + b.y);
    }
    const float2 bin2 = *(const float2*)(b_ih + 2 * H + jg);
    const float2 bhn2 = *(const float2*)(b_hh + 2 * H + jg);

    // Fragment bases
    const uint32_t* Yb0 = smw + YOFF + g * 256;
    const uint32_t* Yb1 = smw + YOFF + (g + 8) * 256;
    const uint32_t* Hb0 = smw + HOFF + g * 256;
    const uint32_t* Hb1 = smw + HOFF + (g + 8) * 256;
    const uint32_t* Wi0 = smw + (nt * 24 + g) * 256;            // +8*256, +16*256 tiles
    const uint32_t* Wh0 = smw + WHH_OFF + (nt * 24 + g) * 256;
    const int xw = g << 2;
    const int kbase = kh * 128;

    __syncthreads();

    int p = 0;
    for (int t = 0; t < L; t++) {
        const float* hcur = g_h[p];
        float* hnxt = g_h[p ^ 1];
        const __nv_bfloat16* hcurB = g_hB[p];
        __nv_bfloat16* hnxtB = g_hB[p ^ 1];

        // h(t) -> SMEM via cp.async
        {
            const __nv_bfloat16* src = hcurB + (size_t)(rg * 16 + pr) * H + ps * 32;
#pragma unroll
            for (int i = 0; i < 4; i++) {
                const int w0 = ps * 16 + 4 * i;
                cp16(smw + HOFF + pr * 256 + (w0 ^ ((pr & 7) << 2)), src + i * 8);
            }
            CP_COMMIT();
        }
        const float2 ho2 = *(const float2*)(hcur + (size_t)grow_e * H + jg);

        CP_WAIT0();
        __syncthreads();

        // y(t+1) register prefetch (hidden behind mma)
        uint4 yp[4];
        const bool hasnext = (t + 1 < L);
        if (hasnext) {
            const uint4* src = (const uint4*)(g_yB + (size_t)((t + 1) * B + rg * 16 + pr) * H + ps * 32);
#pragma unroll
            for (int i = 0; i < 4; i++) yp[i] = src[i];
        }

        float c0[4] = {}, c1[4] = {}, c2i[4] = {}, c2h[4] = {};
#pragma unroll 4
        for (int ck = 0; ck < 16; ck++) {
            const int w = kbase + ck * 8 + tig;
            const int wx0 = w ^ xw;
            const int wx4 = (w + 4) ^ xw;
            uint32_t ay[4], ah[4], bb[2];
            ay[0] = Yb0[wx0]; ay[1] = Yb1[wx0]; ay[2] = Yb0[wx4]; ay[3] = Yb1[wx4];
            ah[0] = Hb0[wx0]; ah[1] = Hb1[wx0]; ah[2] = Hb0[wx4]; ah[3] = Hb1[wx4];
            bb[0] = Wi0[wx0]; bb[1] = Wi0[wx4];
            mma_bf16(c0, ay, bb);
            bb[0] = Wh0[wx0]; bb[1] = Wh0[wx4];
            mma_bf16(c0, ah, bb);
            bb[0] = Wi0[8 * 256 + wx0]; bb[1] = Wi0[8 * 256 + wx4];
            mma_bf16(c1, ay, bb);
            bb[0] = Wh0[8 * 256 + wx0]; bb[1] = Wh0[8 * 256 + wx4];
            mma_bf16(c1, ah, bb);
            bb[0] = Wi0[16 * 256 + wx0]; bb[1] = Wi0[16 * 256 + wx4];
            mma_bf16(c2i, ay, bb);
            bb[0] = Wh0[16 * 256 + wx0]; bb[1] = Wh0[16 * 256 + wx4];
            mma_bf16(c2h, ah, bb);
        }
        __syncthreads();   // A/weight reads done -> Red (over h tile) + y tile writable

        // y(t+1) -> SMEM
        if (hasnext) {
#pragma unroll
            for (int i = 0; i < 4; i++) {
                const int w0 = ps * 16 + 4 * i;
                *(uint4*)(smw + YOFF + pr * 256 + (w0 ^ ((pr & 7) << 2))) = yp[i];
            }
        }

        // Cross-K reduction: kh0 writes, kh1 adds
        const int n0 = nt * 24 + 2 * tig;    // raw col for c0/c1 (r,z strips)
        const int nd = nt * 8 + 2 * tig;     // dim index for n-gate planes
        if (kh == 0) {
            float* Ra = Red + g * RLD;
            float* Rb = Red + (g + 8) * RLD;
            *(float2*)&Ra[n0] = make_float2(c0[0], c0[1]);
            *(float2*)&Rb[n0] = make_float2(c0[2], c0[3]);
            *(float2*)&Ra[n0 + 8] = make_float2(c1[0], c1[1]);
            *(float2*)&Rb[n0 + 8] = make_float2(c1[2], c1[3]);
            *(float2*)&Ra[96 + nd] = make_float2(c2i[0], c2i[1]);
            *(float2*)&Rb[96 + nd] = make_float2(c2i[2], c2i[3]);
            *(float2*)&Ra[128 + nd] = make_float2(c2h[0], c2h[1]);
            *(float2*)&Rb[128 + nd] = make_float2(c2h[2], c2h[3]);
        }
        __syncthreads();
        if (kh == 1) {
            float* Ra = Red + g * RLD;
            float* Rb = Red + (g + 8) * RLD;
            float2 v;
            v = *(float2*)&Ra[n0];       v.x += c0[0]; v.y += c0[1]; *(float2*)&Ra[n0] = v;
            v = *(float2*)&Rb[n0];       v.x += c0[2]; v.y += c0[3]; *(float2*)&Rb[n0] = v;
            v = *(float2*)&Ra[n0 + 8];   v.x += c1[0]; v.y += c1[1]; *(float2*)&Ra[n0 + 8] = v;
            v = *(float2*)&Rb[n0 + 8];   v.x += c1[2]; v.y += c1[3]; *(float2*)&Rb[n0 + 8] = v;
            v = *(float2*)&Ra[96 + nd];  v.x += c2i[0]; v.y += c2i[1]; *(float2*)&Ra[96 + nd] = v;
            v = *(float2*)&Rb[96 + nd];  v.x += c2i[2]; v.y += c2i[3]; *(float2*)&Rb[96 + nd] = v;
            v = *(float2*)&Ra[128 + nd]; v.x += c2h[0]; v.y += c2h[1]; *(float2*)&Ra[128 + nd] = v;
            v = *(float2*)&Rb[128 + nd]; v.x += c2h[2]; v.y += c2h[3]; *(float2*)&Rb[128 + nd] = v;
        }
        __syncthreads();

        // Gates: thread owns (row_e, dims j2, j2+1)
        {
            const float* Rr = Red + row_e * RLD;
            const int rcol = (j2 >> 3) * 24 + (j2 & 7);
            const float2 rp = *(const float2*)&Rr[rcol];
            const float2 zp = *(const float2*)&Rr[rcol + 8];
            const float2 ni = *(const float2*)&Rr[96 + j2];
            const float2 nh = *(const float2*)&Rr[128 + j2];
            const float r0 = 1.0f / (1.0f + __expf(-(rp.x + br2.x)));
            const float r1 = 1.0f / (1.0f + __expf(-(rp.y + br2.y)));
            const float z0 = 1.0f / (1.0f + __expf(-(zp.x + bz2.x)));
            const float z1 = 1.0f / (1.0f + __expf(-(zp.y + bz2.y)));
            const float n0v = tanhf(ni.x + bin2.x + r0 * (nh.x + bhn2.x));
            const float n1v = tanhf(ni.y + bin2.y + r1 * (nh.y + bhn2.y));
            float2 hn;
            hn.x = (1.0f - z0) * n0v + z0 * ho2.x;
            hn.y = (1.0f - z1) * n1v + z1 * ho2.y;
            *(float2*)(hnxt + (size_t)grow_e * H + jg) = hn;
            __nv_bfloat162 hb;
            hb.x = __float2bfloat16_rn(hn.x);
            hb.y = __float2bfloat16_rn(hn.y);
            *(__nv_bfloat162*)(hnxtB + (size_t)grow_e * H + jg) = hb;
        }

        // Row-group barrier (16 CTAs)
        __threadfence();
        __syncthreads();
        if (tid == 0) {
            const unsigned target = (unsigned)(t + 1);
            if (atomicAdd(&g_gcnt[rg], 1u) == GRP - 1) {
                atomicExch(&g_gcnt[rg], 0u);
                __threadfence();
                atomicExch(&g_ggen[rg], target);
            } else {
                while (*(volatile unsigned*)&g_ggen[rg] < target) {}
            }
        }
        __syncthreads();
        p ^= 1;
    }
}

// ---------------------------------------------------------------------------
// Classifier
// ---------------------------------------------------------------------------
__global__ void classifier_kernel(const float* __restrict__ cls_w,
                                  const float* __restrict__ cls_b,
                                  float* __restrict__ out) {
    const int b = blockIdx.x / C;
    const int cc = blockIdx.x % C;
    const float* h = g_h[0] + b * H;
    const float* w = cls_w + cc * H;
    float s = 0.0f;
    for (int k = threadIdx.x; k < H; k += 64) s += h[k] * w[k];
#pragma unroll
    for (int o = 16; o > 0; o >>= 1) s += __shfl_down_sync(0xffffffffu, s, o);
    __shared__ float red[2];
    if ((threadIdx.x & 31) == 0) red[threadIdx.x >> 5] = s;
    __syncthreads();
    if (threadIdx.x == 0) out[b * C + cc] = red[0] + red[1] + cls_b[cc];
}

// ---------------------------------------------------------------------------
// Launch
// ---------------------------------------------------------------------------
extern "C" void kernel_launch(void* const* d_in, const int* in_sizes, int n_in,
                              void* d_out, int out_size) {
    const int*   x      = (const int*)d_in[0];
    const float* conv_w = (const float*)d_in[1];
    const float* conv_b = (const float*)d_in[2];
    const float* w_ih   = (const float*)d_in[3];
    const float* w_hh   = (const float*)d_in[4];
    const float* b_ih   = (const float*)d_in[5];
    const float* b_hh   = (const float*)d_in[6];
    const float* cls_w  = (const float*)d_in[7];
    const float* cls_b  = (const float*)d_in[8];
    float* out = (float*)d_out;

    cudaFuncSetAttribute(gru_kernel, cudaFuncAttributeMaxDynamicSharedMemorySize, GRU_SMEM);

    init_kernel<<<512, 256>>>();
    prep_kernel<<<(H * V * 3 + 255) / 256, 256>>>(conv_w);
    embed_kernel<<<NROW, 128>>>(x, conv_b);
    gru_kernel<<<NGRP * GRP, 256, GRU_SMEM>>>(w_ih, w_hh, b_ih, b_hh);
    classifier_kernel<<<B * C, 64>>>(cls_w, cls_b, out);
}

// round 9
// speedup vs baseline: 2.3586x; 1.2354x over previous
#include <cuda_runtime.h>
#include <cuda_bf16.h>
#include <cstdint>

// Problem constants
constexpr int B = 128, L = 1024, V = 512, H = 512, C = 20;
constexpr int NROW = L * B;        // 131072

// ---------------------------------------------------------------------------
// Device scratch
// ---------------------------------------------------------------------------
__device__ float g_T[3][V][H];                         // transposed conv weights
__device__ __nv_bfloat16 g_yB[(size_t)NROW * H];       // conv output (bf16)
__device__ float g_h[2][B * H];                        // final hidden (fp32, classifier)
__device__ __nv_bfloat16 g_hB[2][B * H];               // hidden state (bf16, exchange)
constexpr int NGRP = 8, GRP = 16;                      // 8 row-groups x 16 dim CTAs
__device__ unsigned g_gcnt[NGRP];
__device__ unsigned g_ggen[NGRP];

// ---------------------------------------------------------------------------
// Helpers
// ---------------------------------------------------------------------------
__device__ __forceinline__ void mma_bf16(float c[4], const uint32_t a[4], const uint32_t b[2]) {
    asm volatile(
        "mma.sync.aligned.m16n8k16.row.col.f32.bf16.bf16.f32 "
        "{%0,%1,%2,%3}, {%4,%5,%6,%7}, {%8,%9}, {%0,%1,%2,%3};\n"
        : "+f"(c[0]), "+f"(c[1]), "+f"(c[2]), "+f"(c[3])
        : "r"(a[0]), "r"(a[1]), "r"(a[2]), "r"(a[3]), "r"(b[0]), "r"(b[1]));
}

__device__ __forceinline__ void cp16(void* dst_smem, const void* src) {
    uint32_t d = (uint32_t)__cvta_generic_to_shared(dst_smem);
    asm volatile("cp.async.cg.shared.global [%0], [%1], 16;" :: "r"(d), "l"(src));
}
#define CP_COMMIT()  asm volatile("cp.async.commit_group;" ::: "memory")
#define CP_WAIT0()   asm volatile("cp.async.wait_group 0;" ::: "memory")

// ---------------------------------------------------------------------------
// Init (runs every launch — graph replays)
// ---------------------------------------------------------------------------
__global__ void init_kernel() {
    const int i = blockIdx.x * blockDim.x + threadIdx.x;
    if (i < 2 * B * H) {
        ((float*)g_h)[i] = 0.0f;
        ((__nv_bfloat16*)g_hB)[i] = __float2bfloat16(0.0f);
    }
    if (i < NGRP) { g_gcnt[i] = 0u; g_ggen[i] = 0u; }
}

// ---------------------------------------------------------------------------
// Prep: transpose conv_w -> g_T
// ---------------------------------------------------------------------------
__global__ void prep_kernel(const float* __restrict__ conv_w) {
    const int idx = blockIdx.x * blockDim.x + threadIdx.x;
    if (idx < H * V * 3) {
        const int k = idx % 3;
        const int v = (idx / 3) % V;
        const int h = idx / (3 * V);
        g_T[k][v][h] = conv_w[idx];
    }
}

// ---------------------------------------------------------------------------
// Embedding "conv" -> bf16 y
// ---------------------------------------------------------------------------
__global__ void embed_kernel(const int* __restrict__ x, const float* __restrict__ conv_b) {
    const int n = blockIdx.x;      // n = t*B + b
    const int t = n >> 7;
    const int b = n & 127;
    const int x0 = x[b * L + t];
    const int xm = (t > 0) ? x[b * L + t - 1] : -1;
    const int xp = (t < L - 1) ? x[b * L + t + 1] : -1;
    const int hb = threadIdx.x * 4;

    float4 acc = *(const float4*)(conv_b + hb);
    {
        const float4 e = *(const float4*)(&g_T[1][x0][hb]);
        acc.x += e.x; acc.y += e.y; acc.z += e.z; acc.w += e.w;
    }
    if (xm >= 0) {
        const float4 e = *(const float4*)(&g_T[0][xm][hb]);
        acc.x += e.x; acc.y += e.y; acc.z += e.z; acc.w += e.w;
    }
    if (xp >= 0) {
        const float4 e = *(const float4*)(&g_T[2][xp][hb]);
        acc.x += e.x; acc.y += e.y; acc.z += e.z; acc.w += e.w;
    }
    __nv_bfloat162 p0, p1;
    p0.x = __float2bfloat16_rn(fmaxf(acc.x, 0.0f));
    p0.y = __float2bfloat16_rn(fmaxf(acc.y, 0.0f));
    p1.x = __float2bfloat16_rn(fmaxf(acc.z, 0.0f));
    p1.y = __float2bfloat16_rn(fmaxf(acc.w, 0.0f));
    *(__nv_bfloat162*)(g_yB + (size_t)n * H + hb) = p0;
    *(__nv_bfloat162*)(g_yB + (size_t)n * H + hb + 2) = p1;
}

// ---------------------------------------------------------------------------
// Fused persistent GRU kernel v8: latency-restructured step.
// Per step: [gi mma (no h needed)] -> [acquire-wait h(t)] -> [cp h, gh mma]
// -> [reduce, gates (h_old in regs), STG bf16 h(t+1)] -> [release-arrive].
// The h exchange latency is hidden under the gi mma of the waiting CTAs.
// Layout identical to v7 (XOR-swizzled weight/y/h tiles, Red aliased on h).
// ---------------------------------------------------------------------------
constexpr int WHH_OFF = 96 * 256;            // 24576 words
constexpr int YOFF = 2 * 96 * 256;           // 49152
constexpr int HOFF = YOFF + 4096;            // 53248
constexpr int GRU_SMEM = (HOFF + 4096) * 4;  // 229,376 B
constexpr int RLD = 164;                     // Red row stride (floats)

__global__ void __launch_bounds__(256, 1) gru_kernel(const float* __restrict__ w_ih,
                                                     const float* __restrict__ w_hh,
                                                     const float* __restrict__ b_ih,
                                                     const float* __restrict__ b_hh) {
    extern __shared__ uint32_t smw[];
    float* Red = (float*)(smw + HOFF);       // aliased over h tile

    const int tid = threadIdx.x, warp = tid >> 5, lane = tid & 31;
    const int g = lane >> 2, tig = lane & 3;
    const int nt = warp >> 1, kh = warp & 1;
    const int rg = blockIdx.x >> 4, dg = blockIdx.x & 15;
    const int pr = tid >> 4, ps = tid & 15;  // cp/sts row + 16-word segment

    // Prologue: y(0) via cp.async
    {
        const __nv_bfloat16* src = g_yB + (size_t)(rg * 16 + pr) * H + ps * 32;
#pragma unroll
        for (int i = 0; i < 4; i++) {
            const int w0 = ps * 16 + 4 * i;
            cp16(smw + YOFF + pr * 256 + (w0 ^ ((pr & 7) << 2)), src + i * 8);
        }
        CP_COMMIT();
    }

    // Weights -> SMEM bf16 with XOR swizzle
    for (int i = tid; i < 2 * 96 * 128; i += 256) {
        const int mat = i / (96 * 128);
        const int rem = i - mat * (96 * 128);
        const int n = rem >> 7, f4 = rem & 127;
        const int tt = n >> 3;
        const int grow = (tt % 3) * H + dg * 32 + (tt / 3) * 8 + (n & 7);
        const float* srcm = mat ? w_hh : w_ih;
        const float4 v = *(const float4*)(srcm + (size_t)grow * H + f4 * 4);
        __nv_bfloat162 q0, q1;
        q0.x = __float2bfloat16_rn(v.x); q0.y = __float2bfloat16_rn(v.y);
        q1.x = __float2bfloat16_rn(v.z); q1.y = __float2bfloat16_rn(v.w);
        const int w0 = (f4 * 2) ^ ((n & 7) << 2);
        uint2 pk;
        pk.x = *(const uint32_t*)&q0;
        pk.y = *(const uint32_t*)&q1;
        *(uint2*)(smw + mat * WHH_OFF + n * 256 + w0) = pk;
    }

    // Gate-phase setup: thread -> (row_e, dim pair j2)
    const int row_e = tid >> 4;
    const int j2 = (tid & 15) * 2;
    const int grow_e = rg * 16 + row_e;
    const int jg = dg * 32 + j2;
    float2 br2, bz2;
    {
        float2 a = *(const float2*)(b_ih + jg), b = *(const float2*)(b_hh + jg);
        br2 = make_float2(a.x + b.x, a.y + b.y);
        a = *(const float2*)(b_ih + H + jg); b = *(const float2*)(b_hh + H + jg);
        bz2 = make_float2(a.x + b.x, a.y + b.y);
    }
    const float2 bin2 = *(const float2*)(b_ih + 2 * H + jg);
    const float2 bhn2 = *(const float2*)(b_hh + 2 * H + jg);

    // Fragment bases
    const uint32_t* Yb0 = smw + YOFF + g * 256;
    const uint32_t* Yb1 = smw + YOFF + (g + 8) * 256;
    const uint32_t* Hb0 = smw + HOFF + g * 256;
    const uint32_t* Hb1 = smw + HOFF + (g + 8) * 256;
    const uint32_t* Wi0 = smw + (nt * 24 + g) * 256;
    const uint32_t* Wh0 = smw + WHH_OFF + (nt * 24 + g) * 256;
    const int xw = g << 2;
    const int kbase = kh * 128;

    __syncthreads();

    float2 ho2 = make_float2(0.0f, 0.0f);   // h_old lives in registers
    int p = 0;
    for (int t = 0; t < L; t++) {
        const bool hasnext = (t + 1 < L);

        // y(t+1) LDG prefetch (issued first; latency hidden under gi mma)
        uint4 yp[4];
        if (hasnext) {
            const uint4* src = (const uint4*)(g_yB + (size_t)((t + 1) * B + rg * 16 + pr) * H + ps * 32);
#pragma unroll
            for (int i = 0; i < 4; i++) yp[i] = src[i];
        }

        // ---- gi mma: y(t) x w_ih (no dependence on h(t)) ----
        float c0[4] = {}, c1[4] = {}, c2i[4] = {}, c2h[4] = {};
#pragma unroll 4
        for (int ck = 0; ck < 16; ck++) {
            const int w = kbase + ck * 8 + tig;
            const int wx0 = w ^ xw;
            const int wx4 = (w + 4) ^ xw;
            uint32_t ay[4], bb[2];
            ay[0] = Yb0[wx0]; ay[1] = Yb1[wx0]; ay[2] = Yb0[wx4]; ay[3] = Yb1[wx4];
            bb[0] = Wi0[wx0]; bb[1] = Wi0[wx4];
            mma_bf16(c0, ay, bb);
            bb[0] = Wi0[8 * 256 + wx0]; bb[1] = Wi0[8 * 256 + wx4];
            mma_bf16(c1, ay, bb);
            bb[0] = Wi0[16 * 256 + wx0]; bb[1] = Wi0[16 * 256 + wx4];
            mma_bf16(c2i, ay, bb);
        }
        __syncthreads();   // all warps done reading y tile

        // Store y(t+1) into the y tile (overlaps the spin below)
        if (hasnext) {
#pragma unroll
            for (int i = 0; i < 4; i++) {
                const int w0 = ps * 16 + 4 * i;
                *(uint4*)(smw + YOFF + pr * 256 + (w0 ^ ((pr & 7) << 2))) = yp[i];
            }
        }

        // ---- acquire-wait: h(t) epoch visible ----
        if (tid == 0) {
            unsigned v;
            do {
                asm volatile("ld.acquire.gpu.u32 %0, [%1];" : "=r"(v) : "l"(g_ggen + rg) : "memory");
            } while ((int)v < t);
        }
        __syncthreads();

        // ---- cp h(t) tile ----
        {
            const __nv_bfloat16* src = g_hB[p] + (size_t)(rg * 16 + pr) * H + ps * 32;
#pragma unroll
            for (int i = 0; i < 4; i++) {
                const int w0 = ps * 16 + 4 * i;
                cp16(smw + HOFF + pr * 256 + (w0 ^ ((pr & 7) << 2)), src + i * 8);
            }
            CP_COMMIT();
        }
        CP_WAIT0();
        __syncthreads();

        // ---- gh mma: h(t) x w_hh ----
#pragma unroll 4
        for (int ck = 0; ck < 16; ck++) {
            const int w = kbase + ck * 8 + tig;
            const int wx0 = w ^ xw;
            const int wx4 = (w + 4) ^ xw;
            uint32_t ah[4], bb[2];
            ah[0] = Hb0[wx0]; ah[1] = Hb1[wx0]; ah[2] = Hb0[wx4]; ah[3] = Hb1[wx4];
            bb[0] = Wh0[wx0]; bb[1] = Wh0[wx4];
            mma_bf16(c0, ah, bb);
            bb[0] = Wh0[8 * 256 + wx0]; bb[1] = Wh0[8 * 256 + wx4];
            mma_bf16(c1, ah, bb);
            bb[0] = Wh0[16 * 256 + wx0]; bb[1] = Wh0[16 * 256 + wx4];
            mma_bf16(c2h, ah, bb);
        }
        __syncthreads();   // h tile reads done -> Red may overwrite

        // Cross-K reduction: kh0 writes, kh1 adds
        const int n0 = nt * 24 + 2 * tig;
        const int nd = nt * 8 + 2 * tig;
        if (kh == 0) {
            float* Ra = Red + g * RLD;
            float* Rb = Red + (g + 8) * RLD;
            *(float2*)&Ra[n0] = make_float2(c0[0], c0[1]);
            *(float2*)&Rb[n0] = make_float2(c0[2], c0[3]);
            *(float2*)&Ra[n0 + 8] = make_float2(c1[0], c1[1]);
            *(float2*)&Rb[n0 + 8] = make_float2(c1[2], c1[3]);
            *(float2*)&Ra[96 + nd] = make_float2(c2i[0], c2i[1]);
            *(float2*)&Rb[96 + nd] = make_float2(c2i[2], c2i[3]);
            *(float2*)&Ra[128 + nd] = make_float2(c2h[0], c2h[1]);
            *(float2*)&Rb[128 + nd] = make_float2(c2h[2], c2h[3]);
        }
        __syncthreads();
        if (kh == 1) {
            float* Ra = Red + g * RLD;
            float* Rb = Red + (g + 8) * RLD;
            float2 v;
            v = *(float2*)&Ra[n0];       v.x += c0[0]; v.y += c0[1]; *(float2*)&Ra[n0] = v;
            v = *(float2*)&Rb[n0];       v.x += c0[2]; v.y += c0[3]; *(float2*)&Rb[n0] = v;
            v = *(float2*)&Ra[n0 + 8];   v.x += c1[0]; v.y += c1[1]; *(float2*)&Ra[n0 + 8] = v;
            v = *(float2*)&Rb[n0 + 8];   v.x += c1[2]; v.y += c1[3]; *(float2*)&Rb[n0 + 8] = v;
            v = *(float2*)&Ra[96 + nd];  v.x += c2i[0]; v.y += c2i[1]; *(float2*)&Ra[96 + nd] = v;
            v = *(float2*)&Rb[96 + nd];  v.x += c2i[2]; v.y += c2i[3]; *(float2*)&Rb[96 + nd] = v;
            v = *(float2*)&Ra[128 + nd]; v.x += c2h[0]; v.y += c2h[1]; *(float2*)&Ra[128 + nd] = v;
            v = *(float2*)&Rb[128 + nd]; v.x += c2h[2]; v.y += c2h[3]; *(float2*)&Rb[128 + nd] = v;
        }
        __syncthreads();

        // Gates: thread owns (row_e, dims j2, j2+1); h_old from registers
        {
            const float* Rr = Red + row_e * RLD;
            const int rcol = (j2 >> 3) * 24 + (j2 & 7);
            const float2 rp = *(const float2*)&Rr[rcol];
            const float2 zp = *(const float2*)&Rr[rcol + 8];
            const float2 ni = *(const float2*)&Rr[96 + j2];
            const float2 nh = *(const float2*)&Rr[128 + j2];
            const float r0 = 1.0f / (1.0f + __expf(-(rp.x + br2.x)));
            const float r1 = 1.0f / (1.0f + __expf(-(rp.y + br2.y)));
            const float z0 = 1.0f / (1.0f + __expf(-(zp.x + bz2.x)));
            const float z1 = 1.0f / (1.0f + __expf(-(zp.y + bz2.y)));
            const float n0v = tanhf(ni.x + bin2.x + r0 * (nh.x + bhn2.x));
            const float n1v = tanhf(ni.y + bin2.y + r1 * (nh.y + bhn2.y));
            float2 hn;
            hn.x = (1.0f - z0) * n0v + z0 * ho2.x;
            hn.y = (1.0f - z1) * n1v + z1 * ho2.y;
            ho2 = hn;
            __nv_bfloat162 hb;
            hb.x = __float2bfloat16_rn(hn.x);
            hb.y = __float2bfloat16_rn(hn.y);
            *(__nv_bfloat162*)(g_hB[p ^ 1] + (size_t)grow_e * H + jg) = hb;
            if (t == L - 1) *(float2*)(g_h[0] + (size_t)grow_e * H + jg) = hn;
        }

        // ---- release-arrive: h(t+1) published ----
        __syncthreads();
        if (tid == 0) {
            unsigned old;
            asm volatile("atom.release.gpu.global.add.u32 %0, [%1], 1;"
                         : "=r"(old) : "l"(g_gcnt + rg) : "memory");
            if (old == GRP - 1) {
                g_gcnt[rg] = 0u;
                const unsigned tgt = (unsigned)(t + 1);
                asm volatile("st.release.gpu.global.u32 [%0], %1;"
                             :: "l"(g_ggen + rg), "r"(tgt) : "memory");
            }
        }
        p ^= 1;
    }
}

// ---------------------------------------------------------------------------
// Classifier
// ---------------------------------------------------------------------------
__global__ void classifier_kernel(const float* __restrict__ cls_w,
                                  const float* __restrict__ cls_b,
                                  float* __restrict__ out) {
    const int b = blockIdx.x / C;
    const int cc = blockIdx.x % C;
    const float* h = g_h[0] + b * H;
    const float* w = cls_w + cc * H;
    float s = 0.0f;
    for (int k = threadIdx.x; k < H; k += 64) s += h[k] * w[k];
#pragma unroll
    for (int o = 16; o > 0; o >>= 1) s += __shfl_down_sync(0xffffffffu, s, o);
    __shared__ float red[2];
    if ((threadIdx.x & 31) == 0) red[threadIdx.x >> 5] = s;
    __syncthreads();
    if (threadIdx.x == 0) out[b * C + cc] = red[0] + red[1] + cls_b[cc];
}

// ---------------------------------------------------------------------------
// Launch
// ---------------------------------------------------------------------------
extern "C" void kernel_launch(void* const* d_in, const int* in_sizes, int n_in,
                              void* d_out, int out_size) {
    const int*   x      = (const int*)d_in[0];
    const float* conv_w = (const float*)d_in[1];
    const float* conv_b = (const float*)d_in[2];
    const float* w_ih   = (const float*)d_in[3];
    const float* w_hh   = (const float*)d_in[4];
    const float* b_ih   = (const float*)d_in[5];
    const float* b_hh   = (const float*)d_in[6];
    const float* cls_w  = (const float*)d_in[7];
    const float* cls_b  = (const float*)d_in[8];
    float* out = (float*)d_out;

    cudaFuncSetAttribute(gru_kernel, cudaFuncAttributeMaxDynamicSharedMemorySize, GRU_SMEM);

    init_kernel<<<512, 256>>>();
    prep_kernel<<<(H * V * 3 + 255) / 256, 256>>>(conv_w);
    embed_kernel<<<NROW, 128>>>(x, conv_b);
    gru_kernel<<<NGRP * GRP, 256, GRU_SMEM>>>(w_ih, w_hh, b_ih, b_hh);
    classifier_kernel<<<B * C, 64>>>(cls_w, cls_b, out);
}